// round 9
// baseline (speedup 1.0000x reference)
#include <cuda_runtime.h>
#include <cuda_bf16.h>
#include <math.h>
#include <stdint.h>

#define BB 256
#define NN 128
#define LL 2048
#define DD 64

__device__ float g_bufA[(size_t)BB * LL * DD];
__device__ float g_bufB[(size_t)BB * LL * DD];
__device__ float g_comp[BB * DD];
__device__ float g_prot[BB * DD];

// ---------------- helpers ----------------
__device__ __forceinline__ float tf32r(float x) {
    float r; asm("cvt.rna.tf32.f32 %0, %1;" : "=f"(r) : "f"(x)); return r;
}
__device__ __forceinline__ void mma_tf32(float* c, float a0, float a1, float a2, float a3,
                                         float b0, float b1) {
    asm volatile(
        "mma.sync.aligned.m16n8k8.row.col.f32.tf32.tf32.f32 "
        "{%0,%1,%2,%3}, {%4,%5,%6,%7}, {%8,%9}, {%0,%1,%2,%3};"
        : "+f"(c[0]), "+f"(c[1]), "+f"(c[2]), "+f"(c[3])
        : "r"(__float_as_uint(a0)), "r"(__float_as_uint(a1)),
          "r"(__float_as_uint(a2)), "r"(__float_as_uint(a3)),
          "r"(__float_as_uint(b0)), "r"(__float_as_uint(b1)));
}
__device__ __forceinline__ void mma_bf16(float* c, uint32_t a0, uint32_t a1,
                                         uint32_t a2, uint32_t a3,
                                         uint32_t b0, uint32_t b1) {
    asm volatile(
        "mma.sync.aligned.m16n8k16.row.col.f32.bf16.bf16.f32 "
        "{%0,%1,%2,%3}, {%4,%5,%6,%7}, {%8,%9}, {%0,%1,%2,%3};"
        : "+f"(c[0]), "+f"(c[1]), "+f"(c[2]), "+f"(c[3])
        : "r"(a0), "r"(a1), "r"(a2), "r"(a3), "r"(b0), "r"(b1));
}
__device__ __forceinline__ uint32_t pbf2(float lo, float hi) {
    __nv_bfloat162 h = __floats2bfloat162_rn(lo, hi);
    return *(uint32_t*)&h;
}

// ---------------- conv: bf16 m16n8k16 Toeplitz, 64-row tiles ----------------
// inS2[s][pair]: bf16x2, pair p holds cols 2p,2p+1 of padded tile (pad 12 left).
// out[m][w] = sum_{i,c} in[m+i-11][c-12] * k[i][c-w-1]
#define ST 52
#define CV_SMEM ((86 * ST + 23 * 40) * 4)

__global__ void __launch_bounds__(128) conv_bf16(
    const float* __restrict__ ck, const float* __restrict__ cb,
    int layer, int srcSel, int gather,
    const int* __restrict__ amino, const float* __restrict__ emb)
{
    extern __shared__ uint32_t cs[];
    uint32_t* inS = cs;             // [86][52] bf16x2
    uint32_t* kP  = cs + 86 * ST;   // [23][2 parity][20]

    const float* in = srcSel ? g_bufB : g_bufA;
    float* out      = srcSel ? g_bufA : g_bufB;

    const int b  = blockIdx.y;
    const int h0 = blockIdx.x * 64;
    const int tid = threadIdx.x;

    for (int idx = tid; idx < 86 * ST; idx += 128) inS[idx] = 0u;
    // Toeplitz taps, two parity-packed copies: par0 entry jo -> pair start d=2jo-8,
    // par1 -> d=2jo-7 (pair = (k[d], k[d+1]), zero outside [0,23))
    const float* kk = ck + layer * 529;
    for (int idx = tid; idx < 23 * 40; idx += 128) {
        int i = idx / 40, r = idx % 40, par = r / 20, jo = r % 20;
        int d = 2 * jo - 8 + par;
        float v0 = (d >= 0 && d < 23) ? kk[i * 23 + d] : 0.f;
        float v1 = (d + 1 >= 0 && d + 1 < 23) ? kk[i * 23 + d + 1] : 0.f;
        kP[idx] = pbf2(v0, v1);
    }
    __syncthreads();

    const float* inb = in + (size_t)b * LL * DD;
    const int* am = amino + b * LL;
    for (int idx = tid; idx < 86 * 16; idx += 128) {
        int s = idx >> 4, q = idx & 15;
        int gh = h0 + s - 11;
        if (gh >= 0 && gh < LL) {
            float4 v;
            if (gather) v = ((const float4*)(emb + (size_t)am[gh] * DD))[q];
            else        v = ((const float4*)(inb + (size_t)gh * DD))[q];
            inS[s * ST + 6 + 2 * q]     = pbf2(v.x, v.y);
            inS[s * ST + 6 + 2 * q + 1] = pbf2(v.z, v.w);
        }
    }
    __syncthreads();

    const int lane = tid & 31, warp = tid >> 5;
    const int grp = lane >> 2, qd = lane & 3;
    const int mbase = warp * 16;

    float acc[8][4];
    #pragma unroll
    for (int n = 0; n < 8; n++)
        #pragma unroll
        for (int e = 0; e < 4; e++) acc[n][e] = 0.f;

    // B tap index: d0 = 2qd - grp - 1; parity(d0) = parity(grp+1)
    const uint32_t* Pbase = kP + ((grp & 1) ? 0 : 20);
    const int j0 = (grp & 1) ? (qd + ((7 - grp) >> 1)) : (qd + 3 - (grp >> 1));

    #pragma unroll 1
    for (int i = 0; i < 23; i++) {
        const uint32_t* P = Pbase + i * 40;
        uint32_t b00 = P[j0], b01 = P[j0 + 4], b10 = P[j0 + 8], b11 = P[j0 + 12];
        const uint32_t* r0 = inS + (mbase + grp + i) * ST + qd;
        const uint32_t* r1 = r0 + 8 * ST;
        uint32_t c0 = r0[0], c1 = r1[0];
        #pragma unroll
        for (int g = 0; g < 10; g++) {
            uint32_t n0 = r0[4 * (g + 1)], n1 = r1[4 * (g + 1)];
            if (g < 8)  mma_bf16(acc[g],     c0, c1, n0, n1, b00, b01);
            if (g >= 2) mma_bf16(acc[g - 2], c0, c1, n0, n1, b10, b11);
            c0 = n0; c1 = n1;
        }
    }

    const float bias = cb[layer];
    float* ob = out + (size_t)b * LL * DD + (size_t)h0 * DD;
    int m0 = mbase + grp;
    #pragma unroll
    for (int n = 0; n < 8; n++) {
        int w = 8 * n + qd * 2;
        float2 v0, v1;
        v0.x = fmaxf(acc[n][0] + bias, 0.f);
        v0.y = fmaxf(acc[n][1] + bias, 0.f);
        v1.x = fmaxf(acc[n][2] + bias, 0.f);
        v1.y = fmaxf(acc[n][3] + bias, 0.f);
        *(float2*)(ob + (size_t)m0 * DD + w) = v0;
        *(float2*)(ob + (size_t)(m0 + 8) * DD + w) = v1;
    }
}

// ---------------- hs GEMM: hs = relu(ps @ W_att^T + b_att) * mask ----------------
#define HS_SMEM ((128 * 68 + 64 * 68 + 64) * 4)

__global__ void __launch_bounds__(128) hs_gemm(
    const float* __restrict__ W_att, const float* __restrict__ b_att,
    const float* __restrict__ amino_mask)
{
    extern __shared__ float hsm[];
    float* psS = hsm;
    float* wS  = hsm + 128 * 68;
    float* bS  = wS + 64 * 68;

    const int b  = blockIdx.y;
    const int l0 = blockIdx.x * 128;
    const int tid = threadIdx.x;
    const float* ps = g_bufB + (size_t)b * LL * DD;

    for (int idx = tid; idx < 128 * 16; idx += 128) {
        int s = idx >> 4, q = idx & 15;
        float4 v = ((const float4*)(ps + (size_t)(l0 + s) * DD))[q];
        v.x = tf32r(v.x); v.y = tf32r(v.y); v.z = tf32r(v.z); v.w = tf32r(v.w);
        *(float4*)(psS + s * 68 + 4 * q) = v;
    }
    for (int idx = tid; idx < 64 * 16; idx += 128) {
        int e = idx >> 4, q = idx & 15;
        float4 v = ((const float4*)(W_att + e * 64))[q];
        v.x = tf32r(v.x); v.y = tf32r(v.y); v.z = tf32r(v.z); v.w = tf32r(v.w);
        *(float4*)(wS + e * 68 + 4 * q) = v;
    }
    if (tid < 64) bS[tid] = b_att[tid];
    __syncthreads();

    const int lane = tid & 31, warp = tid >> 5;
    const int grp = lane >> 2, qd = lane & 3;
    const int mbase = warp * 32;

    float acc[2][8][4];
    #pragma unroll
    for (int rb = 0; rb < 2; rb++)
        #pragma unroll
        for (int n = 0; n < 8; n++)
            #pragma unroll
            for (int e = 0; e < 4; e++) acc[rb][n][e] = 0.f;

    #pragma unroll 1
    for (int ks = 0; ks < 8; ks++) {
        float bf[8][2];
        #pragma unroll
        for (int n = 0; n < 8; n++) {
            const float* wr = wS + (8 * n + grp) * 68 + 8 * ks + qd;
            bf[n][0] = wr[0];
            bf[n][1] = wr[4];
        }
        #pragma unroll
        for (int rb = 0; rb < 2; rb++) {
            const float* ar = psS + (mbase + rb * 16 + grp) * 68 + 8 * ks + qd;
            float a0 = ar[0], a1 = ar[8 * 68], a2 = ar[4], a3 = ar[8 * 68 + 4];
            #pragma unroll
            for (int n = 0; n < 8; n++)
                mma_tf32(acc[rb][n], a0, a1, a2, a3, bf[n][0], bf[n][1]);
        }
    }

    float* hb = g_bufA + (size_t)b * LL * DD;
    const float* mk = amino_mask + b * LL;
    #pragma unroll
    for (int rb = 0; rb < 2; rb++) {
        int l = l0 + mbase + rb * 16 + grp;
        float m0v = mk[l], m1v = mk[l + 8];
        #pragma unroll
        for (int n = 0; n < 8; n++) {
            int e = 8 * n + 2 * qd;
            float2 v0, v1;
            v0.x = fmaxf(acc[rb][n][0] + bS[e], 0.f) * m0v;
            v0.y = fmaxf(acc[rb][n][1] + bS[e + 1], 0.f) * m0v;
            v1.x = fmaxf(acc[rb][n][2] + bS[e], 0.f) * m1v;
            v1.y = fmaxf(acc[rb][n][3] + bS[e + 1], 0.f) * m1v;
            *(float2*)(hb + (size_t)l * DD + e) = v0;
            *(float2*)(hb + (size_t)(l + 8) * DD + e) = v1;
        }
    }
}

// ---------------- attention finalize ----------------
__global__ void __launch_bounds__(256) att_fin(
    const float* __restrict__ amino_mask,
    const float* __restrict__ W_att, const float* __restrict__ b_att)
{
    __shared__ float hv[64], sprot[64], ssum;
    const int b = blockIdx.x, tid = threadIdx.x;

    if (tid < 64) {
        float a = b_att[tid];
        const float* wr = W_att + tid * 64;
        #pragma unroll 4
        for (int d = 0; d < DD; d++) a = fmaf(g_comp[b * DD + d], wr[d], a);
        hv[tid] = fmaxf(a, 0.f);
        sprot[tid] = 0.f;
    }
    if (tid == 0) ssum = 0.f;
    __syncthreads();

    const float* hsb = g_bufA + (size_t)b * LL * DD;
    float prl[64];
    #pragma unroll
    for (int d = 0; d < 64; d++) prl[d] = 0.f;
    float msum = 0.f;

    for (int l = tid; l < LL; l += 256) {
        msum += amino_mask[b * LL + l];
        const float4* xr = (const float4*)(hsb + (size_t)l * DD);
        float4 x4[16];
        #pragma unroll
        for (int q = 0; q < 16; q++) x4[q] = xr[q];
        float wh = 0.f;
        #pragma unroll
        for (int d = 0; d < 64; d++) wh = fmaf(hv[d], ((const float*)x4)[d], wh);
        float w = tanhf(wh);
        #pragma unroll
        for (int d = 0; d < 64; d++) prl[d] = fmaf(w, ((const float*)x4)[d], prl[d]);
    }

    for (int off = 16; off; off >>= 1) msum += __shfl_xor_sync(~0u, msum, off);
    if ((tid & 31) == 0) atomicAdd(&ssum, msum);
    #pragma unroll
    for (int d = 0; d < 64; d++) {
        float v = prl[d];
        for (int off = 16; off; off >>= 1) v += __shfl_xor_sync(~0u, v, off);
        if ((tid & 31) == 0) atomicAdd(&sprot[d], v);
    }
    __syncthreads();
    if (tid < 64) g_prot[b * DD + tid] = sprot[tid] / (ssum + 1e-6f);
}

// ===================== GNN (unchanged) =====================
__global__ void __launch_bounds__(256) gnn_kernel(
    const int* __restrict__ atoms, const float* __restrict__ atoms_mask,
    const float* __restrict__ adj, const float* __restrict__ emb_fp,
    const float* __restrict__ W_gnn, const float* __restrict__ b_gnn)
{
    extern __shared__ float smf[];
    float* xs = smf;
    float* hs = xs + 128 * 68;
    float* Wt = hs + 128 * 68;
    float* bv = Wt + 64 * 68;
    const int b = blockIdx.x, tid = threadIdx.x;

    for (int o = tid; o < NN * DD; o += 256) {
        int n = o >> 6, d = o & 63;
        xs[n * 68 + d] = emb_fp[atoms[b * NN + n] * DD + d];
    }
    for (int layer = 0; layer < 3; layer++) {
        __syncthreads();
        for (int o = tid; o < DD * DD; o += 256) {
            int e = o >> 6, d = o & 63;
            Wt[d * 68 + e] = W_gnn[layer * DD * DD + o];
        }
        if (tid < DD) bv[tid] = b_gnn[layer * DD + tid];
        __syncthreads();
        for (int g = tid; g < NN * 16; g += 256) {
            int n = g >> 4, e4 = (g & 15) * 4;
            float a0 = bv[e4], a1 = bv[e4+1], a2 = bv[e4+2], a3 = bv[e4+3];
            const float* xr = xs + n * 68;
            #pragma unroll 4
            for (int d = 0; d < DD; d++) {
                float x = xr[d];
                float4 w = *(const float4*)(Wt + d * 68 + e4);
                a0 = fmaf(x, w.x, a0); a1 = fmaf(x, w.y, a1);
                a2 = fmaf(x, w.z, a2); a3 = fmaf(x, w.w, a3);
            }
            float* hr = hs + n * 68 + e4;
            hr[0] = fmaxf(a0, 0.f); hr[1] = fmaxf(a1, 0.f);
            hr[2] = fmaxf(a2, 0.f); hr[3] = fmaxf(a3, 0.f);
        }
        __syncthreads();
        const float* adjb = adj + (size_t)b * NN * NN;
        for (int g = tid; g < NN * 16; g += 256) {
            int n = g >> 4, d4 = (g & 15) * 4;
            float* xp = xs + n * 68 + d4;
            float a0 = xp[0], a1 = xp[1], a2 = xp[2], a3 = xp[3];
            const float* ar = adjb + n * NN;
            #pragma unroll 4
            for (int m = 0; m < NN; m++) {
                float av = __ldg(ar + m);
                float4 h = *(const float4*)(hs + m * 68 + d4);
                a0 = fmaf(av, h.x, a0); a1 = fmaf(av, h.y, a1);
                a2 = fmaf(av, h.z, a2); a3 = fmaf(av, h.w, a3);
            }
            xp[0] = a0; xp[1] = a1; xp[2] = a2; xp[3] = a3;
        }
    }
    __syncthreads();
    if (tid < DD) {
        float s = 0.f, ms = 0.f;
        for (int n = 0; n < NN; n++) {
            float m = atoms_mask[b * NN + n];
            s += xs[n * 68 + tid] * m;
            ms += m;
        }
        g_comp[b * DD + tid] = s / (ms + 1e-6f);
    }
}

// ===================== output MLP (unchanged) =====================
__global__ void __launch_bounds__(128) out_kernel(
    const float* __restrict__ W_out, const float* __restrict__ b_out,
    const float* __restrict__ W_int, const float* __restrict__ b_int,
    float* __restrict__ out)
{
    __shared__ float cat[128], nxt[128];
    const int b = blockIdx.x, t = threadIdx.x;
    if (t < 64) { cat[t] = g_comp[b * 64 + t]; cat[64 + t] = g_prot[b * 64 + t]; }
    __syncthreads();
    for (int j = 0; j < 2; j++) {
        float a = b_out[j * 128 + t];
        const float* wr = W_out + j * 16384 + t * 128;
        #pragma unroll 4
        for (int d = 0; d < 128; d++) a = fmaf(cat[d], wr[d], a);
        nxt[t] = fmaxf(a, 0.f);
        __syncthreads();
        cat[t] = nxt[t];
        __syncthreads();
    }
    if (t < 2) {
        float a = b_int[t];
        const float* wr = W_int + t * 128;
        for (int d = 0; d < 128; d++) a = fmaf(cat[d], wr[d], a);
        out[b * 2 + t] = a;
    }
}

// ===========================================================================
extern "C" void kernel_launch(void* const* d_in, const int* in_sizes, int n_in,
                              void* d_out, int out_size)
{
    const int*   atoms      = (const int*)  d_in[0];
    const float* atoms_mask = (const float*)d_in[1];
    const float* adjacency  = (const float*)d_in[2];
    const int*   amino      = (const int*)  d_in[3];
    const float* amino_mask = (const float*)d_in[4];
    const float* emb_fp     = (const float*)d_in[5];
    const float* emb_word   = (const float*)d_in[6];
    const float* W_gnn      = (const float*)d_in[7];
    const float* b_gnn      = (const float*)d_in[8];
    const float* conv_k     = (const float*)d_in[9];
    const float* conv_b     = (const float*)d_in[10];
    const float* W_att      = (const float*)d_in[11];
    const float* b_att      = (const float*)d_in[12];
    const float* W_out      = (const float*)d_in[13];
    const float* b_out      = (const float*)d_in[14];
    const float* W_int      = (const float*)d_in[15];
    const float* b_int      = (const float*)d_in[16];
    float* out = (float*)d_out;

    cudaFuncSetAttribute(gnn_kernel, cudaFuncAttributeMaxDynamicSharedMemorySize, 87296);
    cudaFuncSetAttribute(conv_bf16,  cudaFuncAttributeMaxDynamicSharedMemorySize, CV_SMEM);
    cudaFuncSetAttribute(hs_gemm,    cudaFuncAttributeMaxDynamicSharedMemorySize, HS_SMEM);

    gnn_kernel<<<BB, 256, 87296>>>(atoms, atoms_mask, adjacency, emb_fp, W_gnn, b_gnn);

    dim3 cgrid(LL / 64, BB);
    conv_bf16<<<cgrid, 128, CV_SMEM>>>(conv_k, conv_b, 0, 0, 1, amino, emb_word); // gather -> B
    conv_bf16<<<cgrid, 128, CV_SMEM>>>(conv_k, conv_b, 1, 1, 0, amino, emb_word); // B -> A
    conv_bf16<<<cgrid, 128, CV_SMEM>>>(conv_k, conv_b, 2, 0, 0, amino, emb_word); // A -> B

    dim3 hgrid(LL / 128, BB);
    hs_gemm<<<hgrid, 128, HS_SMEM>>>(W_att, b_att, amino_mask);

    att_fin<<<BB, 256>>>(amino_mask, W_att, b_att);
    out_kernel<<<BB, 128>>>(W_out, b_out, W_int, b_int, out);
}

// round 10
// speedup vs baseline: 1.1061x; 1.1061x over previous
#include <cuda_runtime.h>
#include <cuda_bf16.h>
#include <math.h>
#include <stdint.h>

#define BB 256
#define NN 128
#define LL 2048
#define DD 64

// bf16x2 pair buffers: pair p of row l holds cols 2p, 2p+1
__device__ uint32_t g_pA[(size_t)BB * LL * 32];
__device__ uint32_t g_pB[(size_t)BB * LL * 32];
__device__ float g_comp[BB * DD];

// ---------------- helpers ----------------
__device__ __forceinline__ void mma_bf16(float* c, uint32_t a0, uint32_t a1,
                                         uint32_t a2, uint32_t a3,
                                         uint32_t b0, uint32_t b1) {
    asm volatile(
        "mma.sync.aligned.m16n8k16.row.col.f32.bf16.bf16.f32 "
        "{%0,%1,%2,%3}, {%4,%5,%6,%7}, {%8,%9}, {%0,%1,%2,%3};"
        : "+f"(c[0]), "+f"(c[1]), "+f"(c[2]), "+f"(c[3])
        : "r"(a0), "r"(a1), "r"(a2), "r"(a3), "r"(b0), "r"(b1));
}
__device__ __forceinline__ uint32_t pbf2(float lo, float hi) {
    __nv_bfloat162 h = __floats2bfloat162_rn(lo, hi);
    return *(uint32_t*)&h;
}
__device__ __forceinline__ float2 ubf2(uint32_t p) {
    return __bfloat1622float2(*(__nv_bfloat162*)&p);
}

// ---------------- conv: bf16 m16n8k16 Toeplitz, 64-row tiles ----------------
// out[m][w] = sum_{i,c} in[m+i-11][c-12] * k[i][c-w-1]
// fuse=1 (layer 2): epilogue computes hs = relu(ps@W_att^T+b_att)*mask in-block.
#define ST 52
#define PT 36
#define CV_SMEM_BASE ((86 * ST + 23 * 40) * 4)               // 21568
#define CV_SMEM_FUSE (CV_SMEM_BASE + (2 * 64 * PT + 64) * 4) // 40256

__global__ void __launch_bounds__(128) conv_bf16(
    const float* __restrict__ ck, const float* __restrict__ cb,
    int layer, int srcSel, int gather, int fuse,
    const int* __restrict__ amino, const float* __restrict__ emb,
    const float* __restrict__ W_att, const float* __restrict__ b_att,
    const float* __restrict__ amino_mask)
{
    extern __shared__ uint32_t cs[];
    uint32_t* inS = cs;             // [86][52] bf16x2
    uint32_t* kP  = cs + 86 * ST;   // [23][2 parity][20]
    uint32_t* psT = kP + 23 * 40;   // [64][36]  (fuse only)
    uint32_t* wS  = psT + 64 * PT;  // [64][36]  (fuse only)
    float*    bS  = (float*)(wS + 64 * PT);

    const uint32_t* inp = srcSel ? g_pB : g_pA;
    uint32_t* outp      = srcSel ? g_pA : g_pB;

    const int b  = blockIdx.y;
    const int h0 = blockIdx.x * 64;
    const int tid = threadIdx.x;

    for (int idx = tid; idx < 86 * ST; idx += 128) inS[idx] = 0u;
    const float* kk = ck + layer * 529;
    for (int idx = tid; idx < 23 * 40; idx += 128) {
        int i = idx / 40, r = idx % 40, par = r / 20, jo = r % 20;
        int d = 2 * jo - 8 + par;
        float v0 = (d >= 0 && d < 23) ? kk[i * 23 + d] : 0.f;
        float v1 = (d + 1 >= 0 && d + 1 < 23) ? kk[i * 23 + d + 1] : 0.f;
        kP[idx] = pbf2(v0, v1);
    }
    if (fuse) {
        for (int idx = tid; idx < 64 * 32; idx += 128) {
            int e = idx >> 5, p = idx & 31;
            wS[e * PT + p] = pbf2(W_att[e * 64 + 2 * p], W_att[e * 64 + 2 * p + 1]);
        }
        if (tid < 64) bS[tid] = b_att[tid];
    }

    if (gather) {
        const int* am = amino + b * LL;
        for (int idx = tid; idx < 86 * 16; idx += 128) {
            int s = idx >> 4, q = idx & 15;
            int gh = h0 + s - 11;
            if (gh >= 0 && gh < LL) {
                float4 v = ((const float4*)(emb + (size_t)am[gh] * DD))[q];
                inS[s * ST + 6 + 2 * q]     = pbf2(v.x, v.y);
                inS[s * ST + 6 + 2 * q + 1] = pbf2(v.z, v.w);
            }
        }
    } else {
        const uint32_t* inb = inp + (size_t)b * LL * 32;
        for (int idx = tid; idx < 86 * 8; idx += 128) {
            int s = idx >> 3, q = idx & 7;
            int gh = h0 + s - 11;
            if (gh >= 0 && gh < LL) {
                uint4 v = ((const uint4*)(inb + (size_t)gh * 32))[q];
                uint32_t* p = inS + s * ST + 6 + 4 * q;
                p[0] = v.x; p[1] = v.y; p[2] = v.z; p[3] = v.w;
            }
        }
    }
    __syncthreads();

    const int lane = tid & 31, warp = tid >> 5;
    const int grp = lane >> 2, qd = lane & 3;
    const int mbase = warp * 16;

    float acc[8][4];
    #pragma unroll
    for (int n = 0; n < 8; n++)
        #pragma unroll
        for (int e = 0; e < 4; e++) acc[n][e] = 0.f;

    const uint32_t* Pbase = kP + ((grp & 1) ? 0 : 20);
    const int j0 = (grp & 1) ? (qd + ((7 - grp) >> 1)) : (qd + 3 - (grp >> 1));

    #pragma unroll 1
    for (int i = 0; i < 23; i++) {
        const uint32_t* P = Pbase + i * 40;
        uint32_t b00 = P[j0], b01 = P[j0 + 4], b10 = P[j0 + 8], b11 = P[j0 + 12];
        const uint32_t* r0 = inS + (mbase + grp + i) * ST + qd;
        const uint32_t* r1 = r0 + 8 * ST;
        uint32_t c0 = r0[0], c1 = r1[0];
        #pragma unroll
        for (int g = 0; g < 10; g++) {
            uint32_t n0 = r0[4 * (g + 1)], n1 = r1[4 * (g + 1)];
            if (g < 8)  mma_bf16(acc[g],     c0, c1, n0, n1, b00, b01);
            if (g >= 2) mma_bf16(acc[g - 2], c0, c1, n0, n1, b10, b11);
            c0 = n0; c1 = n1;
        }
    }

    const float bias = cb[layer];
    const int m0 = mbase + grp;

    if (!fuse) {
        uint32_t* ob = outp + ((size_t)b * LL + h0) * 32;
        #pragma unroll
        for (int n = 0; n < 8; n++) {
            int pr = 4 * n + qd;
            ob[(size_t)m0 * 32 + pr] =
                pbf2(fmaxf(acc[n][0] + bias, 0.f), fmaxf(acc[n][1] + bias, 0.f));
            ob[(size_t)(m0 + 8) * 32 + pr] =
                pbf2(fmaxf(acc[n][2] + bias, 0.f), fmaxf(acc[n][3] + bias, 0.f));
        }
        return;
    }

    // ---- fused hs epilogue: ps tile -> smem bf16, then 64x64x64 GEMM ----
    #pragma unroll
    for (int n = 0; n < 8; n++) {
        int pr = 4 * n + qd;
        psT[m0 * PT + pr] =
            pbf2(fmaxf(acc[n][0] + bias, 0.f), fmaxf(acc[n][1] + bias, 0.f));
        psT[(m0 + 8) * PT + pr] =
            pbf2(fmaxf(acc[n][2] + bias, 0.f), fmaxf(acc[n][3] + bias, 0.f));
    }
    __syncthreads();

    float acc2[8][4];
    #pragma unroll
    for (int n = 0; n < 8; n++)
        #pragma unroll
        for (int e = 0; e < 4; e++) acc2[n][e] = 0.f;

    #pragma unroll
    for (int kc = 0; kc < 4; kc++) {
        const uint32_t* ar0 = psT + (mbase + grp) * PT + 8 * kc + qd;
        const uint32_t* ar1 = ar0 + 8 * PT;
        uint32_t a0 = ar0[0], a1 = ar1[0], a2 = ar0[4], a3 = ar1[4];
        #pragma unroll
        for (int n = 0; n < 8; n++) {
            const uint32_t* wr = wS + (8 * n + grp) * PT + 8 * kc + qd;
            mma_bf16(acc2[n], a0, a1, a2, a3, wr[0], wr[4]);
        }
    }

    const float* mk = amino_mask + b * LL;
    int l = h0 + m0;
    float m0v = mk[l], m1v = mk[l + 8];
    uint32_t* hb = outp + ((size_t)b * LL + l) * 32;
    #pragma unroll
    for (int n = 0; n < 8; n++) {
        int e = 8 * n + 2 * qd;
        int pr = 4 * n + qd;
        hb[pr] = pbf2(fmaxf(acc2[n][0] + bS[e], 0.f) * m0v,
                      fmaxf(acc2[n][1] + bS[e + 1], 0.f) * m0v);
        hb[8 * 32 + pr] = pbf2(fmaxf(acc2[n][2] + bS[e], 0.f) * m1v,
                               fmaxf(acc2[n][3] + bS[e + 1], 0.f) * m1v);
    }
}

// ---------------- attention finalize + output MLP ----------------
__global__ void __launch_bounds__(256) att_fin(
    const float* __restrict__ amino_mask,
    const float* __restrict__ W_att, const float* __restrict__ b_att,
    const float* __restrict__ W_out, const float* __restrict__ b_out,
    const float* __restrict__ W_int, const float* __restrict__ b_int,
    float* __restrict__ out)
{
    __shared__ float hv[64], sprot[64], ssum;
    __shared__ float cat[128], nxt[128];
    const int b = blockIdx.x, tid = threadIdx.x;

    if (tid < 64) {
        float a = b_att[tid];
        const float* wr = W_att + tid * 64;
        #pragma unroll 4
        for (int d = 0; d < DD; d++) a = fmaf(g_comp[b * DD + d], wr[d], a);
        hv[tid] = fmaxf(a, 0.f);
        sprot[tid] = 0.f;
    }
    if (tid == 0) ssum = 0.f;
    __syncthreads();

    const uint32_t* hsb = g_pB + (size_t)b * LL * 32;
    float prl[64];
    #pragma unroll
    for (int d = 0; d < 64; d++) prl[d] = 0.f;
    float msum = 0.f;

    for (int l = tid; l < LL; l += 256) {
        msum += amino_mask[b * LL + l];
        const uint4* hp = (const uint4*)(hsb + (size_t)l * 32);
        float x[64];
        #pragma unroll
        for (int q = 0; q < 8; q++) {
            uint4 u = hp[q];
            float2 f;
            f = ubf2(u.x); x[8*q]   = f.x; x[8*q+1] = f.y;
            f = ubf2(u.y); x[8*q+2] = f.x; x[8*q+3] = f.y;
            f = ubf2(u.z); x[8*q+4] = f.x; x[8*q+5] = f.y;
            f = ubf2(u.w); x[8*q+6] = f.x; x[8*q+7] = f.y;
        }
        float wh = 0.f;
        #pragma unroll
        for (int d = 0; d < 64; d++) wh = fmaf(hv[d], x[d], wh);
        float w = tanhf(wh);
        #pragma unroll
        for (int d = 0; d < 64; d++) prl[d] = fmaf(w, x[d], prl[d]);
    }

    for (int off = 16; off; off >>= 1) msum += __shfl_xor_sync(~0u, msum, off);
    if ((tid & 31) == 0) atomicAdd(&ssum, msum);
    #pragma unroll
    for (int d = 0; d < 64; d++) {
        float v = prl[d];
        for (int off = 16; off; off >>= 1) v += __shfl_xor_sync(~0u, v, off);
        if ((tid & 31) == 0) atomicAdd(&sprot[d], v);
    }
    __syncthreads();

    if (tid < 64) {
        cat[tid] = g_comp[b * 64 + tid];
        cat[64 + tid] = sprot[tid] / (ssum + 1e-6f);
    }
    __syncthreads();

    for (int j = 0; j < 2; j++) {
        float a = 0.f;
        if (tid < 128) {
            a = b_out[j * 128 + tid];
            const float* wr = W_out + j * 16384 + tid * 128;
            #pragma unroll 4
            for (int d = 0; d < 128; d++) a = fmaf(cat[d], wr[d], a);
            nxt[tid] = fmaxf(a, 0.f);
        }
        __syncthreads();
        if (tid < 128) cat[tid] = nxt[tid];
        __syncthreads();
    }
    if (tid < 2) {
        float a = b_int[tid];
        const float* wr = W_int + tid * 128;
        for (int d = 0; d < 128; d++) a = fmaf(cat[d], wr[d], a);
        out[b * 2 + tid] = a;
    }
}

// ===================== GNN (unchanged) =====================
__global__ void __launch_bounds__(256) gnn_kernel(
    const int* __restrict__ atoms, const float* __restrict__ atoms_mask,
    const float* __restrict__ adj, const float* __restrict__ emb_fp,
    const float* __restrict__ W_gnn, const float* __restrict__ b_gnn)
{
    extern __shared__ float smf[];
    float* xs = smf;
    float* hs = xs + 128 * 68;
    float* Wt = hs + 128 * 68;
    float* bv = Wt + 64 * 68;
    const int b = blockIdx.x, tid = threadIdx.x;

    for (int o = tid; o < NN * DD; o += 256) {
        int n = o >> 6, d = o & 63;
        xs[n * 68 + d] = emb_fp[atoms[b * NN + n] * DD + d];
    }
    for (int layer = 0; layer < 3; layer++) {
        __syncthreads();
        for (int o = tid; o < DD * DD; o += 256) {
            int e = o >> 6, d = o & 63;
            Wt[d * 68 + e] = W_gnn[layer * DD * DD + o];
        }
        if (tid < DD) bv[tid] = b_gnn[layer * DD + tid];
        __syncthreads();
        for (int g = tid; g < NN * 16; g += 256) {
            int n = g >> 4, e4 = (g & 15) * 4;
            float a0 = bv[e4], a1 = bv[e4+1], a2 = bv[e4+2], a3 = bv[e4+3];
            const float* xr = xs + n * 68;
            #pragma unroll 4
            for (int d = 0; d < DD; d++) {
                float x = xr[d];
                float4 w = *(const float4*)(Wt + d * 68 + e4);
                a0 = fmaf(x, w.x, a0); a1 = fmaf(x, w.y, a1);
                a2 = fmaf(x, w.z, a2); a3 = fmaf(x, w.w, a3);
            }
            float* hr = hs + n * 68 + e4;
            hr[0] = fmaxf(a0, 0.f); hr[1] = fmaxf(a1, 0.f);
            hr[2] = fmaxf(a2, 0.f); hr[3] = fmaxf(a3, 0.f);
        }
        __syncthreads();
        const float* adjb = adj + (size_t)b * NN * NN;
        for (int g = tid; g < NN * 16; g += 256) {
            int n = g >> 4, d4 = (g & 15) * 4;
            float* xp = xs + n * 68 + d4;
            float a0 = xp[0], a1 = xp[1], a2 = xp[2], a3 = xp[3];
            const float* ar = adjb + n * NN;
            #pragma unroll 4
            for (int m = 0; m < NN; m++) {
                float av = __ldg(ar + m);
                float4 h = *(const float4*)(hs + m * 68 + d4);
                a0 = fmaf(av, h.x, a0); a1 = fmaf(av, h.y, a1);
                a2 = fmaf(av, h.z, a2); a3 = fmaf(av, h.w, a3);
            }
            xp[0] = a0; xp[1] = a1; xp[2] = a2; xp[3] = a3;
        }
    }
    __syncthreads();
    if (tid < DD) {
        float s = 0.f, ms = 0.f;
        for (int n = 0; n < NN; n++) {
            float m = atoms_mask[b * NN + n];
            s += xs[n * 68 + tid] * m;
            ms += m;
        }
        g_comp[b * DD + tid] = s / (ms + 1e-6f);
    }
}

// ===========================================================================
extern "C" void kernel_launch(void* const* d_in, const int* in_sizes, int n_in,
                              void* d_out, int out_size)
{
    const int*   atoms      = (const int*)  d_in[0];
    const float* atoms_mask = (const float*)d_in[1];
    const float* adjacency  = (const float*)d_in[2];
    const int*   amino      = (const int*)  d_in[3];
    const float* amino_mask = (const float*)d_in[4];
    const float* emb_fp     = (const float*)d_in[5];
    const float* emb_word   = (const float*)d_in[6];
    const float* W_gnn      = (const float*)d_in[7];
    const float* b_gnn      = (const float*)d_in[8];
    const float* conv_k     = (const float*)d_in[9];
    const float* conv_b     = (const float*)d_in[10];
    const float* W_att      = (const float*)d_in[11];
    const float* b_att      = (const float*)d_in[12];
    const float* W_out      = (const float*)d_in[13];
    const float* b_out      = (const float*)d_in[14];
    const float* W_int      = (const float*)d_in[15];
    const float* b_int      = (const float*)d_in[16];
    float* out = (float*)d_out;

    cudaFuncSetAttribute(gnn_kernel, cudaFuncAttributeMaxDynamicSharedMemorySize, 87296);
    cudaFuncSetAttribute(conv_bf16,  cudaFuncAttributeMaxDynamicSharedMemorySize, CV_SMEM_FUSE);

    gnn_kernel<<<BB, 256, 87296>>>(atoms, atoms_mask, adjacency, emb_fp, W_gnn, b_gnn);

    dim3 cgrid(LL / 64, BB);
    // L0: gather emb -> g_pB
    conv_bf16<<<cgrid, 128, CV_SMEM_BASE>>>(conv_k, conv_b, 0, 0, 1, 0,
        amino, emb_word, W_att, b_att, amino_mask);
    // L1: g_pB -> g_pA
    conv_bf16<<<cgrid, 128, CV_SMEM_BASE>>>(conv_k, conv_b, 1, 1, 0, 0,
        amino, emb_word, W_att, b_att, amino_mask);
    // L2 fused: g_pA -> hs in g_pB
    conv_bf16<<<cgrid, 128, CV_SMEM_FUSE>>>(conv_k, conv_b, 2, 0, 0, 1,
        amino, emb_word, W_att, b_att, amino_mask);

    att_fin<<<BB, 256>>>(amino_mask, W_att, b_att, W_out, b_out, W_int, b_int, out);
}

// round 11
// speedup vs baseline: 1.4740x; 1.3327x over previous
#include <cuda_runtime.h>
#include <cuda_bf16.h>
#include <math.h>
#include <stdint.h>

#define BB 256
#define NN 128
#define LL 2048
#define DD 64

// bf16x2 pair buffers: pair p of row l holds cols 2p, 2p+1
__device__ uint32_t g_pA[(size_t)BB * LL * 32];
__device__ uint32_t g_pB[(size_t)BB * LL * 32];
__device__ float g_comp[BB * DD];

// ---------------- helpers ----------------
__device__ __forceinline__ float tf32r(float x) {
    float r; asm("cvt.rna.tf32.f32 %0, %1;" : "=f"(r) : "f"(x)); return r;
}
__device__ __forceinline__ void mma_tf32(float* c, float a0, float a1, float a2, float a3,
                                         float b0, float b1) {
    asm volatile(
        "mma.sync.aligned.m16n8k8.row.col.f32.tf32.tf32.f32 "
        "{%0,%1,%2,%3}, {%4,%5,%6,%7}, {%8,%9}, {%0,%1,%2,%3};"
        : "+f"(c[0]), "+f"(c[1]), "+f"(c[2]), "+f"(c[3])
        : "r"(__float_as_uint(a0)), "r"(__float_as_uint(a1)),
          "r"(__float_as_uint(a2)), "r"(__float_as_uint(a3)),
          "r"(__float_as_uint(b0)), "r"(__float_as_uint(b1)));
}
__device__ __forceinline__ void mma_bf16(float* c, uint32_t a0, uint32_t a1,
                                         uint32_t a2, uint32_t a3,
                                         uint32_t b0, uint32_t b1) {
    asm volatile(
        "mma.sync.aligned.m16n8k16.row.col.f32.bf16.bf16.f32 "
        "{%0,%1,%2,%3}, {%4,%5,%6,%7}, {%8,%9}, {%0,%1,%2,%3};"
        : "+f"(c[0]), "+f"(c[1]), "+f"(c[2]), "+f"(c[3])
        : "r"(a0), "r"(a1), "r"(a2), "r"(a3), "r"(b0), "r"(b1));
}
__device__ __forceinline__ uint32_t pbf2(float lo, float hi) {
    __nv_bfloat162 h = __floats2bfloat162_rn(lo, hi);
    return *(uint32_t*)&h;
}
__device__ __forceinline__ float2 ubf2(uint32_t p) {
    return __bfloat1622float2(*(__nv_bfloat162*)&p);
}

// ---------------- conv: bf16 m16n8k16 Toeplitz, 64-row tiles ----------------
#define ST 52
#define CV_SMEM ((86 * ST + 23 * 40) * 4)

__global__ void __launch_bounds__(128) conv_bf16(
    const float* __restrict__ ck, const float* __restrict__ cb,
    int layer, int srcSel, int gather,
    const int* __restrict__ amino, const float* __restrict__ emb)
{
    extern __shared__ uint32_t cs[];
    uint32_t* inS = cs;             // [86][52] bf16x2
    uint32_t* kP  = cs + 86 * ST;   // [23][2 parity][20]

    const uint32_t* inp = srcSel ? g_pB : g_pA;
    uint32_t* outp      = srcSel ? g_pA : g_pB;

    const int b  = blockIdx.y;
    const int h0 = blockIdx.x * 64;
    const int tid = threadIdx.x;

    for (int idx = tid; idx < 86 * ST; idx += 128) inS[idx] = 0u;
    const float* kk = ck + layer * 529;
    for (int idx = tid; idx < 23 * 40; idx += 128) {
        int i = idx / 40, r = idx % 40, par = r / 20, jo = r % 20;
        int d = 2 * jo - 8 + par;
        float v0 = (d >= 0 && d < 23) ? kk[i * 23 + d] : 0.f;
        float v1 = (d + 1 >= 0 && d + 1 < 23) ? kk[i * 23 + d + 1] : 0.f;
        kP[idx] = pbf2(v0, v1);
    }

    if (gather) {
        const int* am = amino + b * LL;
        for (int idx = tid; idx < 86 * 16; idx += 128) {
            int s = idx >> 4, q = idx & 15;
            int gh = h0 + s - 11;
            if (gh >= 0 && gh < LL) {
                float4 v = ((const float4*)(emb + (size_t)am[gh] * DD))[q];
                inS[s * ST + 6 + 2 * q]     = pbf2(v.x, v.y);
                inS[s * ST + 6 + 2 * q + 1] = pbf2(v.z, v.w);
            }
        }
    } else {
        const uint32_t* inb = inp + (size_t)b * LL * 32;
        for (int idx = tid; idx < 86 * 8; idx += 128) {
            int s = idx >> 3, q = idx & 7;
            int gh = h0 + s - 11;
            if (gh >= 0 && gh < LL) {
                uint4 v = ((const uint4*)(inb + (size_t)gh * 32))[q];
                uint32_t* p = inS + s * ST + 6 + 4 * q;
                p[0] = v.x; p[1] = v.y; p[2] = v.z; p[3] = v.w;
            }
        }
    }
    __syncthreads();

    const int lane = tid & 31, warp = tid >> 5;
    const int grp = lane >> 2, qd = lane & 3;
    const int mbase = warp * 16;

    float acc[8][4];
    #pragma unroll
    for (int n = 0; n < 8; n++)
        #pragma unroll
        for (int e = 0; e < 4; e++) acc[n][e] = 0.f;

    const uint32_t* Pbase = kP + ((grp & 1) ? 0 : 20);
    const int j0 = (grp & 1) ? (qd + ((7 - grp) >> 1)) : (qd + 3 - (grp >> 1));

    #pragma unroll 1
    for (int i = 0; i < 23; i++) {
        const uint32_t* P = Pbase + i * 40;
        uint32_t b00 = P[j0], b01 = P[j0 + 4], b10 = P[j0 + 8], b11 = P[j0 + 12];
        const uint32_t* r0 = inS + (mbase + grp + i) * ST + qd;
        const uint32_t* r1 = r0 + 8 * ST;
        uint32_t c0 = r0[0], c1 = r1[0];
        #pragma unroll
        for (int g = 0; g < 10; g++) {
            uint32_t n0 = r0[4 * (g + 1)], n1 = r1[4 * (g + 1)];
            if (g < 8)  mma_bf16(acc[g],     c0, c1, n0, n1, b00, b01);
            if (g >= 2) mma_bf16(acc[g - 2], c0, c1, n0, n1, b10, b11);
            c0 = n0; c1 = n1;
        }
    }

    const float bias = cb[layer];
    const int m0 = mbase + grp;
    uint32_t* ob = outp + ((size_t)b * LL + h0) * 32;
    #pragma unroll
    for (int n = 0; n < 8; n++) {
        int pr = 4 * n + qd;
        ob[(size_t)m0 * 32 + pr] =
            pbf2(fmaxf(acc[n][0] + bias, 0.f), fmaxf(acc[n][1] + bias, 0.f));
        ob[(size_t)(m0 + 8) * 32 + pr] =
            pbf2(fmaxf(acc[n][2] + bias, 0.f), fmaxf(acc[n][3] + bias, 0.f));
    }
}

// ---------------- hs GEMM (bf16): hs = relu(ps @ W_att^T + b_att) * mask ----
// ps pairs in g_pB -> hs pairs in g_pA.  64 l-rows per block, 4 warps.
#define PT 36

__global__ void __launch_bounds__(128) hs_gemm_bf(
    const float* __restrict__ W_att, const float* __restrict__ b_att,
    const float* __restrict__ amino_mask)
{
    __shared__ uint32_t psT[64 * PT];
    __shared__ uint32_t wS[64 * PT];
    __shared__ float bS[64];

    const int b  = blockIdx.y;
    const int l0 = blockIdx.x * 64;
    const int tid = threadIdx.x;

    const uint32_t* pb = g_pB + (size_t)b * LL * 32;
    for (int idx = tid; idx < 64 * 8; idx += 128) {
        int s = idx >> 3, q = idx & 7;
        uint4 v = ((const uint4*)(pb + (size_t)(l0 + s) * 32))[q];
        uint32_t* p = psT + s * PT + 4 * q;
        p[0] = v.x; p[1] = v.y; p[2] = v.z; p[3] = v.w;
    }
    for (int idx = tid; idx < 64 * 32; idx += 128) {
        int e = idx >> 5, p = idx & 31;
        wS[e * PT + p] = pbf2(W_att[e * 64 + 2 * p], W_att[e * 64 + 2 * p + 1]);
    }
    if (tid < 64) bS[tid] = b_att[tid];
    __syncthreads();

    const int lane = tid & 31, warp = tid >> 5;
    const int grp = lane >> 2, qd = lane & 3;
    const int mbase = warp * 16;

    float acc[8][4];
    #pragma unroll
    for (int n = 0; n < 8; n++)
        #pragma unroll
        for (int e = 0; e < 4; e++) acc[n][e] = 0.f;

    #pragma unroll
    for (int kc = 0; kc < 4; kc++) {
        const uint32_t* ar0 = psT + (mbase + grp) * PT + 8 * kc + qd;
        const uint32_t* ar1 = ar0 + 8 * PT;
        uint32_t a0 = ar0[0], a1 = ar1[0], a2 = ar0[4], a3 = ar1[4];
        #pragma unroll
        for (int n = 0; n < 8; n++) {
            const uint32_t* wr = wS + (8 * n + grp) * PT + 8 * kc + qd;
            mma_bf16(acc[n], a0, a1, a2, a3, wr[0], wr[4]);
        }
    }

    const float* mk = amino_mask + b * LL;
    int l = l0 + mbase + grp;
    float m0v = mk[l], m1v = mk[l + 8];
    uint32_t* hb = g_pA + ((size_t)b * LL + l) * 32;
    #pragma unroll
    for (int n = 0; n < 8; n++) {
        int e = 8 * n + 2 * qd;
        int pr = 4 * n + qd;
        hb[pr] = pbf2(fmaxf(acc[n][0] + bS[e], 0.f) * m0v,
                      fmaxf(acc[n][1] + bS[e + 1], 0.f) * m0v);
        hb[8 * 32 + pr] = pbf2(fmaxf(acc[n][2] + bS[e], 0.f) * m1v,
                               fmaxf(acc[n][3] + bS[e + 1], 0.f) * m1v);
    }
}

// ---------------- GNN via tf32 mma: 1 block/batch, 128 threads ----------------
// smem: xs[128][68] fp32 | hsT[64][132] | wk = W[64][68] or adjS[128][36] | bv[64]
#define GN_SMEM ((8704 + 8448 + 4608 + 64) * 4)

__global__ void __launch_bounds__(128) gnn_mma(
    const int* __restrict__ atoms, const float* __restrict__ atoms_mask,
    const float* __restrict__ adj, const float* __restrict__ emb_fp,
    const float* __restrict__ W_gnn, const float* __restrict__ b_gnn)
{
    extern __shared__ float sg[];
    float* xs  = sg;            // 128*68
    float* hsT = sg + 8704;     // 64*132
    float* wk  = sg + 17152;    // max(64*68, 128*36)
    float* bv  = sg + 21760;    // 64

    const int b = blockIdx.x, tid = threadIdx.x;
    const int lane = tid & 31, warp = tid >> 5;
    const int grp = lane >> 2, qd = lane & 3;
    const int mbase = warp * 32;

    for (int idx = tid; idx < 128 * 16; idx += 128) {
        int s = idx >> 4, q = idx & 15;
        float4 v = ((const float4*)(emb_fp + (size_t)atoms[b * NN + s] * DD))[q];
        *(float4*)(xs + s * 68 + 4 * q) = v;
    }

    for (int layer = 0; layer < 3; layer++) {
        __syncthreads();
        // stage W (tf32-rounded) + bias
        for (int idx = tid; idx < 64 * 16; idx += 128) {
            int e = idx >> 4, q = idx & 15;
            float4 v = ((const float4*)(W_gnn + layer * 4096 + e * 64))[q];
            v.x = tf32r(v.x); v.y = tf32r(v.y); v.z = tf32r(v.z); v.w = tf32r(v.w);
            *(float4*)(wk + e * 68 + 4 * q) = v;
        }
        if (tid < 64) bv[tid] = b_gnn[layer * 64 + tid];
        __syncthreads();

        // GEMM1: hs = relu(xs @ W^T + b) -> hsT (transposed, tf32-rounded)
        float acc[2][8][4];
        #pragma unroll
        for (int rb = 0; rb < 2; rb++)
            #pragma unroll
            for (int n = 0; n < 8; n++)
                #pragma unroll
                for (int e = 0; e < 4; e++) acc[rb][n][e] = 0.f;

        #pragma unroll 1
        for (int ks = 0; ks < 8; ks++) {
            float bf[8][2];
            #pragma unroll
            for (int n = 0; n < 8; n++) {
                const float* wr = wk + (8 * n + grp) * 68 + 8 * ks + qd;
                bf[n][0] = wr[0]; bf[n][1] = wr[4];
            }
            #pragma unroll
            for (int rb = 0; rb < 2; rb++) {
                const float* ar = xs + (mbase + rb * 16 + grp) * 68 + 8 * ks + qd;
                float a0 = tf32r(ar[0]), a1 = tf32r(ar[8 * 68]);
                float a2 = tf32r(ar[4]), a3 = tf32r(ar[8 * 68 + 4]);
                #pragma unroll
                for (int n = 0; n < 8; n++)
                    mma_tf32(acc[rb][n], a0, a1, a2, a3, bf[n][0], bf[n][1]);
            }
        }
        #pragma unroll
        for (int rb = 0; rb < 2; rb++) {
            int m = mbase + rb * 16 + grp;
            #pragma unroll
            for (int n = 0; n < 8; n++) {
                int e = 8 * n + 2 * qd;
                hsT[e * 132 + m]           = tf32r(fmaxf(acc[rb][n][0] + bv[e], 0.f));
                hsT[(e + 1) * 132 + m]     = tf32r(fmaxf(acc[rb][n][1] + bv[e + 1], 0.f));
                hsT[e * 132 + m + 8]       = tf32r(fmaxf(acc[rb][n][2] + bv[e], 0.f));
                hsT[(e + 1) * 132 + m + 8] = tf32r(fmaxf(acc[rb][n][3] + bv[e + 1], 0.f));
            }
        }

        // GEMM2: xs += adj @ hs   (acc init from xs)
        float acc2[2][8][4];
        #pragma unroll
        for (int rb = 0; rb < 2; rb++) {
            int m = mbase + rb * 16 + grp;
            #pragma unroll
            for (int n = 0; n < 8; n++) {
                int c = 8 * n + 2 * qd;
                float2 v = *(float2*)(xs + m * 68 + c);
                acc2[rb][n][0] = v.x; acc2[rb][n][1] = v.y;
                v = *(float2*)(xs + (m + 8) * 68 + c);
                acc2[rb][n][2] = v.x; acc2[rb][n][3] = v.y;
            }
        }
        const float* adjb = adj + (size_t)b * NN * NN;
        #pragma unroll 1
        for (int g4 = 0; g4 < 4; g4++) {
            __syncthreads();   // wk free (W reads / prev chunk done)
            for (int idx = tid; idx < 128 * 8; idx += 128) {
                int s = idx >> 3, q = idx & 7;
                float4 v = ((const float4*)(adjb + s * 128 + g4 * 32))[q];
                v.x = tf32r(v.x); v.y = tf32r(v.y); v.z = tf32r(v.z); v.w = tf32r(v.w);
                *(float4*)(wk + s * 36 + 4 * q) = v;
            }
            __syncthreads();
            #pragma unroll
            for (int kc = 0; kc < 4; kc++) {
                float bf[8][2];
                #pragma unroll
                for (int n = 0; n < 8; n++) {
                    const float* hr = hsT + (8 * n + grp) * 132 + g4 * 32 + 8 * kc + qd;
                    bf[n][0] = hr[0]; bf[n][1] = hr[4];
                }
                #pragma unroll
                for (int rb = 0; rb < 2; rb++) {
                    const float* ar = wk + (mbase + rb * 16 + grp) * 36 + 8 * kc + qd;
                    float a0 = ar[0], a1 = ar[8 * 36], a2 = ar[4], a3 = ar[8 * 36 + 4];
                    #pragma unroll
                    for (int n = 0; n < 8; n++)
                        mma_tf32(acc2[rb][n], a0, a1, a2, a3, bf[n][0], bf[n][1]);
                }
            }
        }
        // writeback (own rows only)
        #pragma unroll
        for (int rb = 0; rb < 2; rb++) {
            int m = mbase + rb * 16 + grp;
            #pragma unroll
            for (int n = 0; n < 8; n++) {
                int c = 8 * n + 2 * qd;
                *(float2*)(xs + m * 68 + c) = make_float2(acc2[rb][n][0], acc2[rb][n][1]);
                *(float2*)(xs + (m + 8) * 68 + c) = make_float2(acc2[rb][n][2], acc2[rb][n][3]);
            }
        }
    }
    __syncthreads();

    if (tid < DD) {
        float s = 0.f, ms = 0.f;
        for (int n = 0; n < NN; n++) {
            float m = atoms_mask[b * NN + n];
            s += xs[n * 68 + tid] * m;
            ms += m;
        }
        g_comp[b * DD + tid] = s / (ms + 1e-6f);
    }
}

// ---------------- attention finalize + output MLP ----------------
__global__ void __launch_bounds__(256) att_fin(
    const float* __restrict__ amino_mask,
    const float* __restrict__ W_att, const float* __restrict__ b_att,
    const float* __restrict__ W_out, const float* __restrict__ b_out,
    const float* __restrict__ W_int, const float* __restrict__ b_int,
    float* __restrict__ out)
{
    __shared__ float hv[64], sprot[64], ssum;
    __shared__ float cat[128], nxt[128];
    const int b = blockIdx.x, tid = threadIdx.x;

    if (tid < 64) {
        float a = b_att[tid];
        const float* wr = W_att + tid * 64;
        #pragma unroll 4
        for (int d = 0; d < DD; d++) a = fmaf(g_comp[b * DD + d], wr[d], a);
        hv[tid] = fmaxf(a, 0.f);
        sprot[tid] = 0.f;
    }
    if (tid == 0) ssum = 0.f;
    __syncthreads();

    const uint32_t* hsb = g_pA + (size_t)b * LL * 32;
    float prl[64];
    #pragma unroll
    for (int d = 0; d < 64; d++) prl[d] = 0.f;
    float msum = 0.f;

    for (int l = tid; l < LL; l += 256) {
        msum += amino_mask[b * LL + l];
        const uint4* hp = (const uint4*)(hsb + (size_t)l * 32);
        float x[64];
        #pragma unroll
        for (int q = 0; q < 8; q++) {
            uint4 u = hp[q];
            float2 f;
            f = ubf2(u.x); x[8*q]   = f.x; x[8*q+1] = f.y;
            f = ubf2(u.y); x[8*q+2] = f.x; x[8*q+3] = f.y;
            f = ubf2(u.z); x[8*q+4] = f.x; x[8*q+5] = f.y;
            f = ubf2(u.w); x[8*q+6] = f.x; x[8*q+7] = f.y;
        }
        float wh = 0.f;
        #pragma unroll
        for (int d = 0; d < 64; d++) wh = fmaf(hv[d], x[d], wh);
        float w = tanhf(wh);
        #pragma unroll
        for (int d = 0; d < 64; d++) prl[d] = fmaf(w, x[d], prl[d]);
    }

    for (int off = 16; off; off >>= 1) msum += __shfl_xor_sync(~0u, msum, off);
    if ((tid & 31) == 0) atomicAdd(&ssum, msum);
    #pragma unroll
    for (int d = 0; d < 64; d++) {
        float v = prl[d];
        for (int off = 16; off; off >>= 1) v += __shfl_xor_sync(~0u, v, off);
        if ((tid & 31) == 0) atomicAdd(&sprot[d], v);
    }
    __syncthreads();

    if (tid < 64) {
        cat[tid] = g_comp[b * 64 + tid];
        cat[64 + tid] = sprot[tid] / (ssum + 1e-6f);
    }
    __syncthreads();

    for (int j = 0; j < 2; j++) {
        float a = 0.f;
        if (tid < 128) {
            a = b_out[j * 128 + tid];
            const float* wr = W_out + j * 16384 + tid * 128;
            #pragma unroll 4
            for (int d = 0; d < 128; d++) a = fmaf(cat[d], wr[d], a);
            nxt[tid] = fmaxf(a, 0.f);
        }
        __syncthreads();
        if (tid < 128) cat[tid] = nxt[tid];
        __syncthreads();
    }
    if (tid < 2) {
        float a = b_int[tid];
        const float* wr = W_int + tid * 128;
        for (int d = 0; d < 128; d++) a = fmaf(cat[d], wr[d], a);
        out[b * 2 + tid] = a;
    }
}

// ===========================================================================
extern "C" void kernel_launch(void* const* d_in, const int* in_sizes, int n_in,
                              void* d_out, int out_size)
{
    const int*   atoms      = (const int*)  d_in[0];
    const float* atoms_mask = (const float*)d_in[1];
    const float* adjacency  = (const float*)d_in[2];
    const int*   amino      = (const int*)  d_in[3];
    const float* amino_mask = (const float*)d_in[4];
    const float* emb_fp     = (const float*)d_in[5];
    const float* emb_word   = (const float*)d_in[6];
    const float* W_gnn      = (const float*)d_in[7];
    const float* b_gnn      = (const float*)d_in[8];
    const float* conv_k     = (const float*)d_in[9];
    const float* conv_b     = (const float*)d_in[10];
    const float* W_att      = (const float*)d_in[11];
    const float* b_att      = (const float*)d_in[12];
    const float* W_out      = (const float*)d_in[13];
    const float* b_out      = (const float*)d_in[14];
    const float* W_int      = (const float*)d_in[15];
    const float* b_int      = (const float*)d_in[16];
    float* out = (float*)d_out;

    cudaFuncSetAttribute(gnn_mma,   cudaFuncAttributeMaxDynamicSharedMemorySize, GN_SMEM);
    cudaFuncSetAttribute(conv_bf16, cudaFuncAttributeMaxDynamicSharedMemorySize, CV_SMEM);

    gnn_mma<<<BB, 128, GN_SMEM>>>(atoms, atoms_mask, adjacency, emb_fp, W_gnn, b_gnn);

    dim3 cgrid(LL / 64, BB);
    conv_bf16<<<cgrid, 128, CV_SMEM>>>(conv_k, conv_b, 0, 0, 1, amino, emb_word); // emb -> pB
    conv_bf16<<<cgrid, 128, CV_SMEM>>>(conv_k, conv_b, 1, 1, 0, amino, emb_word); // pB -> pA
    conv_bf16<<<cgrid, 128, CV_SMEM>>>(conv_k, conv_b, 2, 0, 0, amino, emb_word); // pA -> pB

    hs_gemm_bf<<<cgrid, 128>>>(W_att, b_att, amino_mask);   // pB -> pA

    att_fin<<<BB, 256>>>(amino_mask, W_att, b_att, W_out, b_out, W_int, b_int, out);
}

// round 13
// speedup vs baseline: 1.8919x; 1.2835x over previous
#include <cuda_runtime.h>
#include <cuda_bf16.h>
#include <math.h>
#include <stdint.h>

#define BB 256
#define NN 128
#define LL 2048
#define DD 64

// bf16x2 pair buffers: pair p of row l holds cols 2p, 2p+1
__device__ uint32_t g_pA[(size_t)BB * LL * 32];
__device__ uint32_t g_pB[(size_t)BB * LL * 32];
__device__ float g_comp[BB * DD];
__device__ float g_prot[BB * DD];
__device__ float g_msum[BB];

// ---------------- helpers ----------------
__device__ __forceinline__ float tf32r(float x) {
    float r; asm("cvt.rna.tf32.f32 %0, %1;" : "=f"(r) : "f"(x)); return r;
}
__device__ __forceinline__ void mma_tf32(float* c, float a0, float a1, float a2, float a3,
                                         float b0, float b1) {
    asm volatile(
        "mma.sync.aligned.m16n8k8.row.col.f32.tf32.tf32.f32 "
        "{%0,%1,%2,%3}, {%4,%5,%6,%7}, {%8,%9}, {%0,%1,%2,%3};"
        : "+f"(c[0]), "+f"(c[1]), "+f"(c[2]), "+f"(c[3])
        : "r"(__float_as_uint(a0)), "r"(__float_as_uint(a1)),
          "r"(__float_as_uint(a2)), "r"(__float_as_uint(a3)),
          "r"(__float_as_uint(b0)), "r"(__float_as_uint(b1)));
}
__device__ __forceinline__ void mma_bf16(float* c, uint32_t a0, uint32_t a1,
                                         uint32_t a2, uint32_t a3,
                                         uint32_t b0, uint32_t b1) {
    asm volatile(
        "mma.sync.aligned.m16n8k16.row.col.f32.bf16.bf16.f32 "
        "{%0,%1,%2,%3}, {%4,%5,%6,%7}, {%8,%9}, {%0,%1,%2,%3};"
        : "+f"(c[0]), "+f"(c[1]), "+f"(c[2]), "+f"(c[3])
        : "r"(a0), "r"(a1), "r"(a2), "r"(a3), "r"(b0), "r"(b1));
}
__device__ __forceinline__ uint32_t pbf2(float lo, float hi) {
    __nv_bfloat162 h = __floats2bfloat162_rn(lo, hi);
    return *(uint32_t*)&h;
}

// ---------------- conv: bf16 m16n8k16 Toeplitz, 64-row tiles (unchanged) ----
#define ST 52
#define CV_SMEM ((86 * ST + 23 * 40) * 4)

__global__ void __launch_bounds__(128) conv_bf16(
    const float* __restrict__ ck, const float* __restrict__ cb,
    int layer, int srcSel, int gather,
    const int* __restrict__ amino, const float* __restrict__ emb)
{
    extern __shared__ uint32_t cs[];
    uint32_t* inS = cs;             // [86][52] bf16x2
    uint32_t* kP  = cs + 86 * ST;   // [23][2 parity][20]

    const uint32_t* inp = srcSel ? g_pB : g_pA;
    uint32_t* outp      = srcSel ? g_pA : g_pB;

    const int b  = blockIdx.y;
    const int h0 = blockIdx.x * 64;
    const int tid = threadIdx.x;

    for (int idx = tid; idx < 86 * ST; idx += 128) inS[idx] = 0u;
    const float* kk = ck + layer * 529;
    for (int idx = tid; idx < 23 * 40; idx += 128) {
        int i = idx / 40, r = idx % 40, par = r / 20, jo = r % 20;
        int d = 2 * jo - 8 + par;
        float v0 = (d >= 0 && d < 23) ? kk[i * 23 + d] : 0.f;
        float v1 = (d + 1 >= 0 && d + 1 < 23) ? kk[i * 23 + d + 1] : 0.f;
        kP[idx] = pbf2(v0, v1);
    }

    if (gather) {
        const int* am = amino + b * LL;
        for (int idx = tid; idx < 86 * 16; idx += 128) {
            int s = idx >> 4, q = idx & 15;
            int gh = h0 + s - 11;
            if (gh >= 0 && gh < LL) {
                float4 v = ((const float4*)(emb + (size_t)am[gh] * DD))[q];
                inS[s * ST + 6 + 2 * q]     = pbf2(v.x, v.y);
                inS[s * ST + 6 + 2 * q + 1] = pbf2(v.z, v.w);
            }
        }
    } else {
        const uint32_t* inb = inp + (size_t)b * LL * 32;
        for (int idx = tid; idx < 86 * 8; idx += 128) {
            int s = idx >> 3, q = idx & 7;
            int gh = h0 + s - 11;
            if (gh >= 0 && gh < LL) {
                uint4 v = ((const uint4*)(inb + (size_t)gh * 32))[q];
                uint32_t* p = inS + s * ST + 6 + 4 * q;
                p[0] = v.x; p[1] = v.y; p[2] = v.z; p[3] = v.w;
            }
        }
    }
    __syncthreads();

    const int lane = tid & 31, warp = tid >> 5;
    const int grp = lane >> 2, qd = lane & 3;
    const int mbase = warp * 16;

    float acc[8][4];
    #pragma unroll
    for (int n = 0; n < 8; n++)
        #pragma unroll
        for (int e = 0; e < 4; e++) acc[n][e] = 0.f;

    const uint32_t* Pbase = kP + ((grp & 1) ? 0 : 20);
    const int j0 = (grp & 1) ? (qd + ((7 - grp) >> 1)) : (qd + 3 - (grp >> 1));

    #pragma unroll 1
    for (int i = 0; i < 23; i++) {
        const uint32_t* P = Pbase + i * 40;
        uint32_t b00 = P[j0], b01 = P[j0 + 4], b10 = P[j0 + 8], b11 = P[j0 + 12];
        const uint32_t* r0 = inS + (mbase + grp + i) * ST + qd;
        const uint32_t* r1 = r0 + 8 * ST;
        uint32_t c0 = r0[0], c1 = r1[0];
        #pragma unroll
        for (int g = 0; g < 10; g++) {
            uint32_t n0 = r0[4 * (g + 1)], n1 = r1[4 * (g + 1)];
            if (g < 8)  mma_bf16(acc[g],     c0, c1, n0, n1, b00, b01);
            if (g >= 2) mma_bf16(acc[g - 2], c0, c1, n0, n1, b10, b11);
            c0 = n0; c1 = n1;
        }
    }

    const float bias = cb[layer];
    const int m0 = mbase + grp;
    uint32_t* ob = outp + ((size_t)b * LL + h0) * 32;
    #pragma unroll
    for (int n = 0; n < 8; n++) {
        int pr = 4 * n + qd;
        ob[(size_t)m0 * 32 + pr] =
            pbf2(fmaxf(acc[n][0] + bias, 0.f), fmaxf(acc[n][1] + bias, 0.f));
        ob[(size_t)(m0 + 8) * 32 + pr] =
            pbf2(fmaxf(acc[n][2] + bias, 0.f), fmaxf(acc[n][3] + bias, 0.f));
    }
}

// ---------------- hs GEMM + fused attention pooling ----------------
// hs = relu(ps @ W_att^T + b_att)*mask (bf16 GEMM, smem only), then
// w = tanh(hv . hs_row); atomically accumulate sum_l w*hs and mask-sum.
#define PT 36

__global__ void __launch_bounds__(128) hs_pool(
    const float* __restrict__ W_att, const float* __restrict__ b_att,
    const float* __restrict__ amino_mask)
{
    __shared__ uint32_t psT[64 * PT];
    __shared__ uint32_t wS[64 * PT];
    __shared__ float bS[64], hv[64], compS[64], wrow[64];
    __shared__ float hsS[64 * 69];
    __shared__ float msum_s;

    const int b  = blockIdx.y;
    const int l0 = blockIdx.x * 64;
    const int tid = threadIdx.x;

    const uint32_t* pb = g_pB + (size_t)b * LL * 32;
    for (int idx = tid; idx < 64 * 8; idx += 128) {
        int s = idx >> 3, q = idx & 7;
        uint4 v = ((const uint4*)(pb + (size_t)(l0 + s) * 32))[q];
        uint32_t* p = psT + s * PT + 4 * q;
        p[0] = v.x; p[1] = v.y; p[2] = v.z; p[3] = v.w;
    }
    for (int idx = tid; idx < 64 * 32; idx += 128) {
        int e = idx >> 5, p = idx & 31;
        wS[e * PT + p] = pbf2(W_att[e * 64 + 2 * p], W_att[e * 64 + 2 * p + 1]);
    }
    if (tid < 64) { bS[tid] = b_att[tid]; compS[tid] = g_comp[b * 64 + tid]; }
    if (tid == 0) msum_s = 0.f;
    __syncthreads();

    // hv = relu(W_att @ comp + b)
    if (tid < 64) {
        float a = bS[tid];
        const float* wr = W_att + tid * 64;
        #pragma unroll 4
        for (int d = 0; d < 64; d++) a = fmaf(compS[d], wr[d], a);
        hv[tid] = fmaxf(a, 0.f);
    }

    const int lane = tid & 31, warp = tid >> 5;
    const int grp = lane >> 2, qd = lane & 3;
    const int mbase = warp * 16;

    float acc[8][4];
    #pragma unroll
    for (int n = 0; n < 8; n++)
        #pragma unroll
        for (int e = 0; e < 4; e++) acc[n][e] = 0.f;

    #pragma unroll
    for (int kc = 0; kc < 4; kc++) {
        const uint32_t* ar0 = psT + (mbase + grp) * PT + 8 * kc + qd;
        const uint32_t* ar1 = ar0 + 8 * PT;
        uint32_t a0 = ar0[0], a1 = ar1[0], a2 = ar0[4], a3 = ar1[4];
        #pragma unroll
        for (int n = 0; n < 8; n++) {
            const uint32_t* wr = wS + (8 * n + grp) * PT + 8 * kc + qd;
            mma_bf16(acc[n], a0, a1, a2, a3, wr[0], wr[4]);
        }
    }

    const float* mk = amino_mask + b * LL;
    const int l = mbase + grp;                 // local row in [0,64)
    float m0v = mk[l0 + l], m1v = mk[l0 + l + 8];
    #pragma unroll
    for (int n = 0; n < 8; n++) {
        int e = 8 * n + 2 * qd;
        hsS[l * 69 + e]           = fmaxf(acc[n][0] + bS[e], 0.f) * m0v;
        hsS[l * 69 + e + 1]       = fmaxf(acc[n][1] + bS[e + 1], 0.f) * m0v;
        hsS[(l + 8) * 69 + e]     = fmaxf(acc[n][2] + bS[e], 0.f) * m1v;
        hsS[(l + 8) * 69 + e + 1] = fmaxf(acc[n][3] + bS[e + 1], 0.f) * m1v;
    }
    __syncthreads();

    // per-row attention weight
    if (tid < 64) {
        float wh = 0.f;
        #pragma unroll 4
        for (int d = 0; d < 64; d++) wh = fmaf(hv[d], hsS[tid * 69 + d], wh);
        wrow[tid] = tanhf(wh);
    }
    // mask sum
    float mv = (tid < 64) ? mk[l0 + tid] : 0.f;
    for (int off = 16; off; off >>= 1) mv += __shfl_xor_sync(~0u, mv, off);
    if (lane == 0 && warp < 2) atomicAdd(&msum_s, mv);
    __syncthreads();

    // pooled sum per dim
    if (tid < 64) {
        float p = 0.f;
        #pragma unroll 4
        for (int row = 0; row < 64; row++) p = fmaf(wrow[row], hsS[row * 69 + tid], p);
        atomicAdd(&g_prot[b * 64 + tid], p);
    }
    if (tid == 0) atomicAdd(&g_msum[b], msum_s);
}

__global__ void zero_prot() {
    int i = blockIdx.x * 256 + threadIdx.x;
    if (i < BB * 64) g_prot[i] = 0.f;
    if (i < BB) g_msum[i] = 0.f;
}

// ---------------- GNN via split-tf32 mma: 1 block/batch, 128 threads ----------
// smem: xs[128][68] | hsT[64][132] | wk = W[64][68] or adjS[128][36] | bv[64]
#define GN_SMEM ((8704 + 8448 + 4608 + 64) * 4)

__global__ void __launch_bounds__(128) gnn_mma(
    const int* __restrict__ atoms, const float* __restrict__ atoms_mask,
    const float* __restrict__ adj, const float* __restrict__ emb_fp,
    const float* __restrict__ W_gnn, const float* __restrict__ b_gnn)
{
    extern __shared__ float sg[];
    float* xs  = sg;            // 128*68
    float* hsT = sg + 8704;     // 64*132 (fp32, exact)
    float* wk  = sg + 17152;    // max(64*68, 128*36)
    float* bv  = sg + 21760;    // 64

    const int b = blockIdx.x, tid = threadIdx.x;
    const int lane = tid & 31, warp = tid >> 5;
    const int grp = lane >> 2, qd = lane & 3;
    const int mbase = warp * 32;

    for (int idx = tid; idx < 128 * 16; idx += 128) {
        int s = idx >> 4, q = idx & 15;
        float4 v = ((const float4*)(emb_fp + (size_t)atoms[b * NN + s] * DD))[q];
        *(float4*)(xs + s * 68 + 4 * q) = v;
    }

    for (int layer = 0; layer < 3; layer++) {
        __syncthreads();
        for (int idx = tid; idx < 64 * 16; idx += 128) {
            int e = idx >> 4, q = idx & 15;
            *(float4*)(wk + e * 68 + 4 * q) =
                ((const float4*)(W_gnn + layer * 4096 + e * 64))[q];
        }
        if (tid < 64) bv[tid] = b_gnn[layer * 64 + tid];
        __syncthreads();

        // GEMM1: hs = relu(xs @ W^T + b), 3-term split tf32
        float acc[2][8][4];
        #pragma unroll
        for (int rb = 0; rb < 2; rb++)
            #pragma unroll
            for (int n = 0; n < 8; n++)
                #pragma unroll
                for (int e = 0; e < 4; e++) acc[rb][n][e] = 0.f;

        #pragma unroll 1
        for (int ks = 0; ks < 8; ks++) {
            float bh[8][2], bl[8][2];
            #pragma unroll
            for (int n = 0; n < 8; n++) {
                const float* wr = wk + (8 * n + grp) * 68 + 8 * ks + qd;
                float w0 = wr[0], w1 = wr[4];
                bh[n][0] = tf32r(w0); bl[n][0] = tf32r(w0 - bh[n][0]);
                bh[n][1] = tf32r(w1); bl[n][1] = tf32r(w1 - bh[n][1]);
            }
            #pragma unroll
            for (int rb = 0; rb < 2; rb++) {
                const float* ar = xs + (mbase + rb * 16 + grp) * 68 + 8 * ks + qd;
                float x0 = ar[0], x1 = ar[8 * 68], x2 = ar[4], x3 = ar[8 * 68 + 4];
                float ah0 = tf32r(x0), al0 = tf32r(x0 - ah0);
                float ah1 = tf32r(x1), al1 = tf32r(x1 - ah1);
                float ah2 = tf32r(x2), al2 = tf32r(x2 - ah2);
                float ah3 = tf32r(x3), al3 = tf32r(x3 - ah3);
                #pragma unroll
                for (int n = 0; n < 8; n++) {
                    mma_tf32(acc[rb][n], ah0, ah1, ah2, ah3, bh[n][0], bh[n][1]);
                    mma_tf32(acc[rb][n], al0, al1, al2, al3, bh[n][0], bh[n][1]);
                    mma_tf32(acc[rb][n], ah0, ah1, ah2, ah3, bl[n][0], bl[n][1]);
                }
            }
        }
        #pragma unroll
        for (int rb = 0; rb < 2; rb++) {
            int m = mbase + rb * 16 + grp;
            #pragma unroll
            for (int n = 0; n < 8; n++) {
                int e = 8 * n + 2 * qd;
                hsT[e * 132 + m]           = fmaxf(acc[rb][n][0] + bv[e], 0.f);
                hsT[(e + 1) * 132 + m]     = fmaxf(acc[rb][n][1] + bv[e + 1], 0.f);
                hsT[e * 132 + m + 8]       = fmaxf(acc[rb][n][2] + bv[e], 0.f);
                hsT[(e + 1) * 132 + m + 8] = fmaxf(acc[rb][n][3] + bv[e + 1], 0.f);
            }
        }

        // GEMM2: xs += adj @ hs, 3-term split tf32
        float acc2[2][8][4];
        #pragma unroll
        for (int rb = 0; rb < 2; rb++) {
            int m = mbase + rb * 16 + grp;
            #pragma unroll
            for (int n = 0; n < 8; n++) {
                int c = 8 * n + 2 * qd;
                float2 v = *(float2*)(xs + m * 68 + c);
                acc2[rb][n][0] = v.x; acc2[rb][n][1] = v.y;
                v = *(float2*)(xs + (m + 8) * 68 + c);
                acc2[rb][n][2] = v.x; acc2[rb][n][3] = v.y;
            }
        }
        const float* adjb = adj + (size_t)b * NN * NN;
        #pragma unroll 1
        for (int g4 = 0; g4 < 4; g4++) {
            __syncthreads();
            for (int idx = tid; idx < 128 * 8; idx += 128) {
                int s = idx >> 3, q = idx & 7;
                *(float4*)(wk + s * 36 + 4 * q) =
                    ((const float4*)(adjb + s * 128 + g4 * 32))[q];
            }
            __syncthreads();
            #pragma unroll
            for (int kc = 0; kc < 4; kc++) {
                float bh[8][2], bl[8][2];
                #pragma unroll
                for (int n = 0; n < 8; n++) {
                    const float* hr = hsT + (8 * n + grp) * 132 + g4 * 32 + 8 * kc + qd;
                    float h0 = hr[0], h1 = hr[4];
                    bh[n][0] = tf32r(h0); bl[n][0] = tf32r(h0 - bh[n][0]);
                    bh[n][1] = tf32r(h1); bl[n][1] = tf32r(h1 - bh[n][1]);
                }
                #pragma unroll
                for (int rb = 0; rb < 2; rb++) {
                    const float* ar = wk + (mbase + rb * 16 + grp) * 36 + 8 * kc + qd;
                    float x0 = ar[0], x1 = ar[8 * 36], x2 = ar[4], x3 = ar[8 * 36 + 4];
                    float ah0 = tf32r(x0), al0 = tf32r(x0 - ah0);
                    float ah1 = tf32r(x1), al1 = tf32r(x1 - ah1);
                    float ah2 = tf32r(x2), al2 = tf32r(x2 - ah2);
                    float ah3 = tf32r(x3), al3 = tf32r(x3 - ah3);
                    #pragma unroll
                    for (int n = 0; n < 8; n++) {
                        mma_tf32(acc2[rb][n], ah0, ah1, ah2, ah3, bh[n][0], bh[n][1]);
                        mma_tf32(acc2[rb][n], al0, al1, al2, al3, bh[n][0], bh[n][1]);
                        mma_tf32(acc2[rb][n], ah0, ah1, ah2, ah3, bl[n][0], bl[n][1]);
                    }
                }
            }
        }
        #pragma unroll
        for (int rb = 0; rb < 2; rb++) {
            int m = mbase + rb * 16 + grp;
            #pragma unroll
            for (int n = 0; n < 8; n++) {
                int c = 8 * n + 2 * qd;
                *(float2*)(xs + m * 68 + c) = make_float2(acc2[rb][n][0], acc2[rb][n][1]);
                *(float2*)(xs + (m + 8) * 68 + c) = make_float2(acc2[rb][n][2], acc2[rb][n][3]);
            }
        }
    }
    __syncthreads();

    if (tid < DD) {
        float s = 0.f, ms = 0.f;
        for (int n = 0; n < NN; n++) {
            float m = atoms_mask[b * NN + n];
            s += xs[n * 68 + tid] * m;
            ms += m;
        }
        g_comp[b * DD + tid] = s / (ms + 1e-6f);
    }
}

// ---------------- final: cat -> MLP -> out ----------------
__global__ void __launch_bounds__(128) out_fin(
    const float* __restrict__ W_out, const float* __restrict__ b_out,
    const float* __restrict__ W_int, const float* __restrict__ b_int,
    float* __restrict__ out)
{
    __shared__ float cat[128], nxt[128];
    const int b = blockIdx.x, tid = threadIdx.x;
    if (tid < 64) {
        cat[tid] = g_comp[b * 64 + tid];
        cat[64 + tid] = g_prot[b * 64 + tid] / (g_msum[b] + 1e-6f);
    }
    __syncthreads();
    for (int j = 0; j < 2; j++) {
        float a = b_out[j * 128 + tid];
        const float* wr = W_out + j * 16384 + tid * 128;
        #pragma unroll 4
        for (int d = 0; d < 128; d++) a = fmaf(cat[d], wr[d], a);
        nxt[tid] = fmaxf(a, 0.f);
        __syncthreads();
        cat[tid] = nxt[tid];
        __syncthreads();
    }
    if (tid < 2) {
        float a = b_int[tid];
        const float* wr = W_int + tid * 128;
        for (int d = 0; d < 128; d++) a = fmaf(cat[d], wr[d], a);
        out[b * 2 + tid] = a;
    }
}

// ===========================================================================
extern "C" void kernel_launch(void* const* d_in, const int* in_sizes, int n_in,
                              void* d_out, int out_size)
{
    const int*   atoms      = (const int*)  d_in[0];
    const float* atoms_mask = (const float*)d_in[1];
    const float* adjacency  = (const float*)d_in[2];
    const int*   amino      = (const int*)  d_in[3];
    const float* amino_mask = (const float*)d_in[4];
    const float* emb_fp     = (const float*)d_in[5];
    const float* emb_word   = (const float*)d_in[6];
    const float* W_gnn      = (const float*)d_in[7];
    const float* b_gnn      = (const float*)d_in[8];
    const float* conv_k     = (const float*)d_in[9];
    const float* conv_b     = (const float*)d_in[10];
    const float* W_att      = (const float*)d_in[11];
    const float* b_att      = (const float*)d_in[12];
    const float* W_out      = (const float*)d_in[13];
    const float* b_out      = (const float*)d_in[14];
    const float* W_int      = (const float*)d_in[15];
    const float* b_int      = (const float*)d_in[16];
    float* out = (float*)d_out;

    cudaFuncSetAttribute(gnn_mma,   cudaFuncAttributeMaxDynamicSharedMemorySize, GN_SMEM);
    cudaFuncSetAttribute(conv_bf16, cudaFuncAttributeMaxDynamicSharedMemorySize, CV_SMEM);

    gnn_mma<<<BB, 128, GN_SMEM>>>(atoms, atoms_mask, adjacency, emb_fp, W_gnn, b_gnn);
    zero_prot<<<64, 256>>>();

    dim3 cgrid(LL / 64, BB);
    conv_bf16<<<cgrid, 128, CV_SMEM>>>(conv_k, conv_b, 0, 0, 1, amino, emb_word); // emb -> pB
    conv_bf16<<<cgrid, 128, CV_SMEM>>>(conv_k, conv_b, 1, 1, 0, amino, emb_word); // pB -> pA
    conv_bf16<<<cgrid, 128, CV_SMEM>>>(conv_k, conv_b, 2, 0, 0, amino, emb_word); // pA -> pB

    hs_pool<<<cgrid, 128>>>(W_att, b_att, amino_mask);   // pB -> pooled g_prot

    out_fin<<<BB, 128>>>(W_out, b_out, W_int, b_int, out);
}

// round 15
// speedup vs baseline: 1.9223x; 1.0160x over previous
#include <cuda_runtime.h>
#include <cuda_bf16.h>
#include <math.h>
#include <stdint.h>

#define BB 256
#define NN 128
#define LL 2048
#define DD 64

// bf16x2 pair buffers: pair p of row l holds cols 2p, 2p+1
__device__ uint32_t g_pA[(size_t)BB * LL * 32];
__device__ uint32_t g_pB[(size_t)BB * LL * 32];
__device__ float g_comp[BB * DD];
__device__ float g_prot[BB * DD];
__device__ float g_msum[BB];

// ---------------- helpers ----------------
__device__ __forceinline__ float tf32r(float x) {
    float r; asm("cvt.rna.tf32.f32 %0, %1;" : "=f"(r) : "f"(x)); return r;
}
__device__ __forceinline__ void mma_tf32(float* c, float a0, float a1, float a2, float a3,
                                         float b0, float b1) {
    asm volatile(
        "mma.sync.aligned.m16n8k8.row.col.f32.tf32.tf32.f32 "
        "{%0,%1,%2,%3}, {%4,%5,%6,%7}, {%8,%9}, {%0,%1,%2,%3};"
        : "+f"(c[0]), "+f"(c[1]), "+f"(c[2]), "+f"(c[3])
        : "r"(__float_as_uint(a0)), "r"(__float_as_uint(a1)),
          "r"(__float_as_uint(a2)), "r"(__float_as_uint(a3)),
          "r"(__float_as_uint(b0)), "r"(__float_as_uint(b1)));
}
__device__ __forceinline__ void mma_bf16(float* c, uint32_t a0, uint32_t a1,
                                         uint32_t a2, uint32_t a3,
                                         uint32_t b0, uint32_t b1) {
    asm volatile(
        "mma.sync.aligned.m16n8k16.row.col.f32.bf16.bf16.f32 "
        "{%0,%1,%2,%3}, {%4,%5,%6,%7}, {%8,%9}, {%0,%1,%2,%3};"
        : "+f"(c[0]), "+f"(c[1]), "+f"(c[2]), "+f"(c[3])
        : "r"(a0), "r"(a1), "r"(a2), "r"(a3), "r"(b0), "r"(b1));
}
__device__ __forceinline__ uint32_t pbf2(float lo, float hi) {
    __nv_bfloat162 h = __floats2bfloat162_rn(lo, hi);
    return *(uint32_t*)&h;
}

// ---------------- conv: bf16 m16n8k16 Toeplitz, 64-row tiles (unchanged) ----
#define ST 52
#define CV_SMEM ((86 * ST + 23 * 40) * 4)

__global__ void __launch_bounds__(128) conv_bf16(
    const float* __restrict__ ck, const float* __restrict__ cb,
    int layer, int srcSel, int gather,
    const int* __restrict__ amino, const float* __restrict__ emb)
{
    extern __shared__ uint32_t cs[];
    uint32_t* inS = cs;             // [86][52] bf16x2
    uint32_t* kP  = cs + 86 * ST;   // [23][2 parity][20]

    const uint32_t* inp = srcSel ? g_pB : g_pA;
    uint32_t* outp      = srcSel ? g_pA : g_pB;

    const int b  = blockIdx.y;
    const int h0 = blockIdx.x * 64;
    const int tid = threadIdx.x;

    for (int idx = tid; idx < 86 * ST; idx += 128) inS[idx] = 0u;
    const float* kk = ck + layer * 529;
    for (int idx = tid; idx < 23 * 40; idx += 128) {
        int i = idx / 40, r = idx % 40, par = r / 20, jo = r % 20;
        int d = 2 * jo - 8 + par;
        float v0 = (d >= 0 && d < 23) ? kk[i * 23 + d] : 0.f;
        float v1 = (d + 1 >= 0 && d + 1 < 23) ? kk[i * 23 + d + 1] : 0.f;
        kP[idx] = pbf2(v0, v1);
    }

    if (gather) {
        const int* am = amino + b * LL;
        for (int idx = tid; idx < 86 * 16; idx += 128) {
            int s = idx >> 4, q = idx & 15;
            int gh = h0 + s - 11;
            if (gh >= 0 && gh < LL) {
                float4 v = ((const float4*)(emb + (size_t)am[gh] * DD))[q];
                inS[s * ST + 6 + 2 * q]     = pbf2(v.x, v.y);
                inS[s * ST + 6 + 2 * q + 1] = pbf2(v.z, v.w);
            }
        }
    } else {
        const uint32_t* inb = inp + (size_t)b * LL * 32;
        for (int idx = tid; idx < 86 * 8; idx += 128) {
            int s = idx >> 3, q = idx & 7;
            int gh = h0 + s - 11;
            if (gh >= 0 && gh < LL) {
                uint4 v = ((const uint4*)(inb + (size_t)gh * 32))[q];
                uint32_t* p = inS + s * ST + 6 + 4 * q;
                p[0] = v.x; p[1] = v.y; p[2] = v.z; p[3] = v.w;
            }
        }
    }
    __syncthreads();

    const int lane = tid & 31, warp = tid >> 5;
    const int grp = lane >> 2, qd = lane & 3;
    const int mbase = warp * 16;

    float acc[8][4];
    #pragma unroll
    for (int n = 0; n < 8; n++)
        #pragma unroll
        for (int e = 0; e < 4; e++) acc[n][e] = 0.f;

    const uint32_t* Pbase = kP + ((grp & 1) ? 0 : 20);
    const int j0 = (grp & 1) ? (qd + ((7 - grp) >> 1)) : (qd + 3 - (grp >> 1));

    #pragma unroll 1
    for (int i = 0; i < 23; i++) {
        const uint32_t* P = Pbase + i * 40;
        uint32_t b00 = P[j0], b01 = P[j0 + 4], b10 = P[j0 + 8], b11 = P[j0 + 12];
        const uint32_t* r0 = inS + (mbase + grp + i) * ST + qd;
        const uint32_t* r1 = r0 + 8 * ST;
        uint32_t c0 = r0[0], c1 = r1[0];
        #pragma unroll
        for (int g = 0; g < 10; g++) {
            uint32_t n0 = r0[4 * (g + 1)], n1 = r1[4 * (g + 1)];
            if (g < 8)  mma_bf16(acc[g],     c0, c1, n0, n1, b00, b01);
            if (g >= 2) mma_bf16(acc[g - 2], c0, c1, n0, n1, b10, b11);
            c0 = n0; c1 = n1;
        }
    }

    const float bias = cb[layer];
    const int m0 = mbase + grp;
    uint32_t* ob = outp + ((size_t)b * LL + h0) * 32;
    #pragma unroll
    for (int n = 0; n < 8; n++) {
        int pr = 4 * n + qd;
        ob[(size_t)m0 * 32 + pr] =
            pbf2(fmaxf(acc[n][0] + bias, 0.f), fmaxf(acc[n][1] + bias, 0.f));
        ob[(size_t)(m0 + 8) * 32 + pr] =
            pbf2(fmaxf(acc[n][2] + bias, 0.f), fmaxf(acc[n][3] + bias, 0.f));
    }
}

// ---------------- hs GEMM + fused attention pooling (unchanged) ------------
#define PT 36

__global__ void __launch_bounds__(128) hs_pool(
    const float* __restrict__ W_att, const float* __restrict__ b_att,
    const float* __restrict__ amino_mask)
{
    __shared__ uint32_t psT[64 * PT];
    __shared__ uint32_t wS[64 * PT];
    __shared__ float bS[64], hv[64], compS[64], wrow[64];
    __shared__ float hsS[64 * 69];
    __shared__ float msum_s;

    const int b  = blockIdx.y;
    const int l0 = blockIdx.x * 64;
    const int tid = threadIdx.x;

    const uint32_t* pb = g_pB + (size_t)b * LL * 32;
    for (int idx = tid; idx < 64 * 8; idx += 128) {
        int s = idx >> 3, q = idx & 7;
        uint4 v = ((const uint4*)(pb + (size_t)(l0 + s) * 32))[q];
        uint32_t* p = psT + s * PT + 4 * q;
        p[0] = v.x; p[1] = v.y; p[2] = v.z; p[3] = v.w;
    }
    for (int idx = tid; idx < 64 * 32; idx += 128) {
        int e = idx >> 5, p = idx & 31;
        wS[e * PT + p] = pbf2(W_att[e * 64 + 2 * p], W_att[e * 64 + 2 * p + 1]);
    }
    if (tid < 64) { bS[tid] = b_att[tid]; compS[tid] = g_comp[b * 64 + tid]; }
    if (tid == 0) msum_s = 0.f;
    __syncthreads();

    if (tid < 64) {
        float a = bS[tid];
        const float* wr = W_att + tid * 64;
        #pragma unroll 4
        for (int d = 0; d < 64; d++) a = fmaf(compS[d], wr[d], a);
        hv[tid] = fmaxf(a, 0.f);
    }

    const int lane = tid & 31, warp = tid >> 5;
    const int grp = lane >> 2, qd = lane & 3;
    const int mbase = warp * 16;

    float acc[8][4];
    #pragma unroll
    for (int n = 0; n < 8; n++)
        #pragma unroll
        for (int e = 0; e < 4; e++) acc[n][e] = 0.f;

    #pragma unroll
    for (int kc = 0; kc < 4; kc++) {
        const uint32_t* ar0 = psT + (mbase + grp) * PT + 8 * kc + qd;
        const uint32_t* ar1 = ar0 + 8 * PT;
        uint32_t a0 = ar0[0], a1 = ar1[0], a2 = ar0[4], a3 = ar1[4];
        #pragma unroll
        for (int n = 0; n < 8; n++) {
            const uint32_t* wr = wS + (8 * n + grp) * PT + 8 * kc + qd;
            mma_bf16(acc[n], a0, a1, a2, a3, wr[0], wr[4]);
        }
    }

    const float* mk = amino_mask + b * LL;
    const int l = mbase + grp;
    float m0v = mk[l0 + l], m1v = mk[l0 + l + 8];
    #pragma unroll
    for (int n = 0; n < 8; n++) {
        int e = 8 * n + 2 * qd;
        hsS[l * 69 + e]           = fmaxf(acc[n][0] + bS[e], 0.f) * m0v;
        hsS[l * 69 + e + 1]       = fmaxf(acc[n][1] + bS[e + 1], 0.f) * m0v;
        hsS[(l + 8) * 69 + e]     = fmaxf(acc[n][2] + bS[e], 0.f) * m1v;
        hsS[(l + 8) * 69 + e + 1] = fmaxf(acc[n][3] + bS[e + 1], 0.f) * m1v;
    }
    __syncthreads();

    if (tid < 64) {
        float wh = 0.f;
        #pragma unroll 4
        for (int d = 0; d < 64; d++) wh = fmaf(hv[d], hsS[tid * 69 + d], wh);
        wrow[tid] = tanhf(wh);
    }
    float mv = (tid < 64) ? mk[l0 + tid] : 0.f;
    for (int off = 16; off; off >>= 1) mv += __shfl_xor_sync(~0u, mv, off);
    if (lane == 0 && warp < 2) atomicAdd(&msum_s, mv);
    __syncthreads();

    if (tid < 64) {
        float p = 0.f;
        #pragma unroll 4
        for (int row = 0; row < 64; row++) p = fmaf(wrow[row], hsS[row * 69 + tid], p);
        atomicAdd(&g_prot[b * 64 + tid], p);
    }
    if (tid == 0) atomicAdd(&g_msum[b], msum_s);
}

__global__ void zero_prot() {
    int i = blockIdx.x * 256 + threadIdx.x;
    if (i < BB * 64) g_prot[i] = 0.f;
    if (i < BB) g_msum[i] = 0.f;
}

// ---------------- GNN via split-tf32 mma: 1 block/batch, 256 threads ---------
// smem: xs[128][68] | hsT[64][132] | wk = W[64][68] or adjS[128][36] | bv[64]
#define GN_SMEM ((8704 + 8448 + 4608 + 64) * 4)

__global__ void __launch_bounds__(256) gnn_mma(
    const int* __restrict__ atoms, const float* __restrict__ atoms_mask,
    const float* __restrict__ adj, const float* __restrict__ emb_fp,
    const float* __restrict__ W_gnn, const float* __restrict__ b_gnn)
{
    extern __shared__ float sg[];
    float* xs  = sg;            // 128*68
    float* hsT = sg + 8704;     // 64*132 (fp32, exact)
    float* wk  = sg + 17152;    // max(64*68, 128*36)
    float* bv  = sg + 21760;    // 64

    const int b = blockIdx.x, tid = threadIdx.x;
    const int lane = tid & 31, warp = tid >> 5;       // 8 warps
    const int grp = lane >> 2, qd = lane & 3;
    const int mbase = warp * 16;                      // 16 rows per warp

    for (int idx = tid; idx < 128 * 16; idx += 256) {
        int s = idx >> 4, q = idx & 15;
        float4 v = ((const float4*)(emb_fp + (size_t)atoms[b * NN + s] * DD))[q];
        *(float4*)(xs + s * 68 + 4 * q) = v;
    }

    for (int layer = 0; layer < 3; layer++) {
        __syncthreads();
        for (int idx = tid; idx < 64 * 16; idx += 256) {
            int e = idx >> 4, q = idx & 15;
            *(float4*)(wk + e * 68 + 4 * q) =
                ((const float4*)(W_gnn + layer * 4096 + e * 64))[q];
        }
        if (tid < 64) bv[tid] = b_gnn[layer * 64 + tid];
        __syncthreads();

        // GEMM1: hs = relu(xs @ W^T + b), 3-term split tf32
        float acc[8][4];
        #pragma unroll
        for (int n = 0; n < 8; n++)
            #pragma unroll
            for (int e = 0; e < 4; e++) acc[n][e] = 0.f;

        #pragma unroll 1
        for (int ks = 0; ks < 8; ks++) {
            float bh[8][2], bl[8][2];
            #pragma unroll
            for (int n = 0; n < 8; n++) {
                const float* wr = wk + (8 * n + grp) * 68 + 8 * ks + qd;
                float w0 = wr[0], w1 = wr[4];
                bh[n][0] = tf32r(w0); bl[n][0] = tf32r(w0 - bh[n][0]);
                bh[n][1] = tf32r(w1); bl[n][1] = tf32r(w1 - bh[n][1]);
            }
            const float* ar = xs + (mbase + grp) * 68 + 8 * ks + qd;
            float x0 = ar[0], x1 = ar[8 * 68], x2 = ar[4], x3 = ar[8 * 68 + 4];
            float ah0 = tf32r(x0), al0 = tf32r(x0 - ah0);
            float ah1 = tf32r(x1), al1 = tf32r(x1 - ah1);
            float ah2 = tf32r(x2), al2 = tf32r(x2 - ah2);
            float ah3 = tf32r(x3), al3 = tf32r(x3 - ah3);
            #pragma unroll
            for (int n = 0; n < 8; n++) {
                mma_tf32(acc[n], ah0, ah1, ah2, ah3, bh[n][0], bh[n][1]);
                mma_tf32(acc[n], al0, al1, al2, al3, bh[n][0], bh[n][1]);
                mma_tf32(acc[n], ah0, ah1, ah2, ah3, bl[n][0], bl[n][1]);
            }
        }
        {
            int m = mbase + grp;
            #pragma unroll
            for (int n = 0; n < 8; n++) {
                int e = 8 * n + 2 * qd;
                hsT[e * 132 + m]           = fmaxf(acc[n][0] + bv[e], 0.f);
                hsT[(e + 1) * 132 + m]     = fmaxf(acc[n][1] + bv[e + 1], 0.f);
                hsT[e * 132 + m + 8]       = fmaxf(acc[n][2] + bv[e], 0.f);
                hsT[(e + 1) * 132 + m + 8] = fmaxf(acc[n][3] + bv[e + 1], 0.f);
            }
        }

        // GEMM2: xs += adj @ hs, 3-term split tf32
        float acc2[8][4];
        {
            int m = mbase + grp;
            #pragma unroll
            for (int n = 0; n < 8; n++) {
                int c = 8 * n + 2 * qd;
                float2 v = *(float2*)(xs + m * 68 + c);
                acc2[n][0] = v.x; acc2[n][1] = v.y;
                v = *(float2*)(xs + (m + 8) * 68 + c);
                acc2[n][2] = v.x; acc2[n][3] = v.y;
            }
        }
        const float* adjb = adj + (size_t)b * NN * NN;
        #pragma unroll 1
        for (int g4 = 0; g4 < 4; g4++) {
            __syncthreads();
            for (int idx = tid; idx < 128 * 8; idx += 256) {
                int s = idx >> 3, q = idx & 7;
                *(float4*)(wk + s * 36 + 4 * q) =
                    ((const float4*)(adjb + s * 128 + g4 * 32))[q];
            }
            __syncthreads();
            #pragma unroll
            for (int kc = 0; kc < 4; kc++) {
                float bh[8][2], bl[8][2];
                #pragma unroll
                for (int n = 0; n < 8; n++) {
                    const float* hr = hsT + (8 * n + grp) * 132 + g4 * 32 + 8 * kc + qd;
                    float h0 = hr[0], h1 = hr[4];
                    bh[n][0] = tf32r(h0); bl[n][0] = tf32r(h0 - bh[n][0]);
                    bh[n][1] = tf32r(h1); bl[n][1] = tf32r(h1 - bh[n][1]);
                }
                const float* ar = wk + (mbase + grp) * 36 + 8 * kc + qd;
                float x0 = ar[0], x1 = ar[8 * 36], x2 = ar[4], x3 = ar[8 * 36 + 4];
                float ah0 = tf32r(x0), al0 = tf32r(x0 - ah0);
                float ah1 = tf32r(x1), al1 = tf32r(x1 - ah1);
                float ah2 = tf32r(x2), al2 = tf32r(x2 - ah2);
                float ah3 = tf32r(x3), al3 = tf32r(x3 - ah3);
                #pragma unroll
                for (int n = 0; n < 8; n++) {
                    mma_tf32(acc2[n], ah0, ah1, ah2, ah3, bh[n][0], bh[n][1]);
                    mma_tf32(acc2[n], al0, al1, al2, al3, bh[n][0], bh[n][1]);
                    mma_tf32(acc2[n], ah0, ah1, ah2, ah3, bl[n][0], bl[n][1]);
                }
            }
        }
        {
            int m = mbase + grp;
            #pragma unroll
            for (int n = 0; n < 8; n++) {
                int c = 8 * n + 2 * qd;
                *(float2*)(xs + m * 68 + c) = make_float2(acc2[n][0], acc2[n][1]);
                *(float2*)(xs + (m + 8) * 68 + c) = make_float2(acc2[n][2], acc2[n][3]);
            }
        }
    }
    __syncthreads();

    if (tid < DD) {
        float s = 0.f, ms = 0.f;
        for (int n = 0; n < NN; n++) {
            float m = atoms_mask[b * NN + n];
            s += xs[n * 68 + tid] * m;
            ms += m;
        }
        g_comp[b * DD + tid] = s / (ms + 1e-6f);
    }
}

// ---------------- final: cat -> MLP -> out ----------------
__global__ void __launch_bounds__(128) out_fin(
    const float* __restrict__ W_out, const float* __restrict__ b_out,
    const float* __restrict__ W_int, const float* __restrict__ b_int,
    float* __restrict__ out)
{
    __shared__ float cat[128], nxt[128];
    const int b = blockIdx.x, tid = threadIdx.x;
    if (tid < 64) {
        cat[tid] = g_comp[b * 64 + tid];
        cat[64 + tid] = g_prot[b * 64 + tid] / (g_msum[b] + 1e-6f);
    }
    __syncthreads();
    for (int j = 0; j < 2; j++) {
        float a = b_out[j * 128 + tid];
        const float* wr = W_out + j * 16384 + tid * 128;
        #pragma unroll 4
        for (int d = 0; d < 128; d++) a = fmaf(cat[d], wr[d], a);
        nxt[tid] = fmaxf(a, 0.f);
        __syncthreads();
        cat[tid] = nxt[tid];
        __syncthreads();
    }
    if (tid < 2) {
        float a = b_int[tid];
        const float* wr = W_int + tid * 128;
        for (int d = 0; d < 128; d++) a = fmaf(cat[d], wr[d], a);
        out[b * 2 + tid] = a;
    }
}

// ===========================================================================
extern "C" void kernel_launch(void* const* d_in, const int* in_sizes, int n_in,
                              void* d_out, int out_size)
{
    const int*   atoms      = (const int*)  d_in[0];
    const float* atoms_mask = (const float*)d_in[1];
    const float* adjacency  = (const float*)d_in[2];
    const int*   amino      = (const int*)  d_in[3];
    const float* amino_mask = (const float*)d_in[4];
    const float* emb_fp     = (const float*)d_in[5];
    const float* emb_word   = (const float*)d_in[6];
    const float* W_gnn      = (const float*)d_in[7];
    const float* b_gnn      = (const float*)d_in[8];
    const float* conv_k     = (const float*)d_in[9];
    const float* conv_b     = (const float*)d_in[10];
    const float* W_att      = (const float*)d_in[11];
    const float* b_att      = (const float*)d_in[12];
    const float* W_out      = (const float*)d_in[13];
    const float* b_out      = (const float*)d_in[14];
    const float* W_int      = (const float*)d_in[15];
    const float* b_int      = (const float*)d_in[16];
    float* out = (float*)d_out;

    static cudaStream_t s1 = nullptr;
    static cudaEvent_t evF = nullptr, evJ = nullptr;
    if (s1 == nullptr) {
        cudaStreamCreateWithFlags(&s1, cudaStreamNonBlocking);
        cudaEventCreateWithFlags(&evF, cudaEventDisableTiming);
        cudaEventCreateWithFlags(&evJ, cudaEventDisableTiming);
        cudaFuncSetAttribute(gnn_mma,   cudaFuncAttributeMaxDynamicSharedMemorySize, GN_SMEM);
        cudaFuncSetAttribute(conv_bf16, cudaFuncAttributeMaxDynamicSharedMemorySize, CV_SMEM);
    }

    // fork: GNN + prot-zero on side stream, conv chain on main stream
    cudaEventRecord(evF, 0);
    cudaStreamWaitEvent(s1, evF, 0);

    gnn_mma<<<BB, 256, GN_SMEM, s1>>>(atoms, atoms_mask, adjacency, emb_fp, W_gnn, b_gnn);
    zero_prot<<<64, 256, 0, s1>>>();

    dim3 cgrid(LL / 64, BB);
    conv_bf16<<<cgrid, 128, CV_SMEM>>>(conv_k, conv_b, 0, 0, 1, amino, emb_word); // emb -> pB
    conv_bf16<<<cgrid, 128, CV_SMEM>>>(conv_k, conv_b, 1, 1, 0, amino, emb_word); // pB -> pA
    conv_bf16<<<cgrid, 128, CV_SMEM>>>(conv_k, conv_b, 2, 0, 0, amino, emb_word); // pA -> pB

    // join before hs_pool (needs g_comp + g_prot zeroed + conv output)
    cudaEventRecord(evJ, s1);
    cudaStreamWaitEvent(0, evJ, 0);

    hs_pool<<<cgrid, 128>>>(W_att, b_att, amino_mask);   // pB -> pooled g_prot
    out_fin<<<BB, 128>>>(W_out, b_out, W_int, b_int, out);
}